// round 6
// baseline (speedup 1.0000x reference)
#include <cuda_runtime.h>
#include <cstdint>

#define NN 50000
#define NE 640000
#define EMB 128
#define SCAN_BLOCKS 196   // 196*256 = 50176 >= NN
#define NB_TILE 391       // (NN+127)/128

// ---- scratch (device globals; zero-initialized at load, re-zeroed each launch) ----
__device__ float g_hA[NN * EMB];      // 25.6 MB
__device__ float g_hB[NN * EMB];      // 25.6 MB
__device__ float g_norm_src[NN];
__device__ float g_norm_dst[NN];
__device__ int   g_deg_src[NN];       // zeroed at end of scanB each launch
__device__ int   g_deg_dst[NN];
__device__ int   g_row_ptr[NN + 1];
__device__ int   g_cursor[NN];
__device__ int2  g_edge[NE];          // (src, __float_as_int(w)) packed
__device__ int   g_part[SCAN_BLOCKS];

// ---------------------------------------------------------------
__global__ void k_count(const int* __restrict__ src, const int* __restrict__ dst) {
    int e = blockIdx.x * blockDim.x + threadIdx.x;
    if (e < NE) {
        atomicAdd(&g_deg_src[__ldg(&src[e])], 1);
        atomicAdd(&g_deg_dst[__ldg(&dst[e])], 1);
    }
}

__global__ void k_scanA() {
    __shared__ int sh[256];
    int i = blockIdx.x * 256 + threadIdx.x;
    int d = (i < NN) ? g_deg_dst[i] : 0;
    sh[threadIdx.x] = d;
    __syncthreads();
    #pragma unroll
    for (int off = 128; off; off >>= 1) {
        if (threadIdx.x < off) sh[threadIdx.x] += sh[threadIdx.x + off];
        __syncthreads();
    }
    if (threadIdx.x == 0) g_part[blockIdx.x] = sh[0];
}

__global__ void k_scanB() {
    __shared__ int sh[256];
    __shared__ int pre;
    int tid = threadIdx.x;
    int b = blockIdx.x;
    int pv = (tid < b) ? g_part[tid] : 0;
    sh[tid] = pv;
    __syncthreads();
    #pragma unroll
    for (int off = 128; off; off >>= 1) {
        if (tid < off) sh[tid] += sh[tid + off];
        __syncthreads();
    }
    if (tid == 0) pre = sh[0];
    __syncthreads();
    int prefix = pre;
    __syncthreads();

    int i = b * 256 + tid;
    int d = (i < NN) ? g_deg_dst[i] : 0;
    sh[tid] = d;
    __syncthreads();
    #pragma unroll
    for (int off = 1; off < 256; off <<= 1) {
        int v = (tid >= off) ? sh[tid - off] : 0;
        __syncthreads();
        sh[tid] += v;
        __syncthreads();
    }
    int incl = sh[tid];
    int excl = incl - d;
    if (i < NN) {
        int base = prefix + excl;
        g_row_ptr[i] = base;
        g_cursor[i]  = base;
        if (i == NN - 1) g_row_ptr[NN] = prefix + incl;
        int ds = g_deg_src[i];
        g_norm_dst[i] = rsqrtf((float)max(d, 1));
        g_norm_src[i] = rsqrtf((float)max(ds, 1));
        g_deg_dst[i] = 0;
        g_deg_src[i] = 0;
    }
}

__global__ void k_fill(const int* __restrict__ src, const int* __restrict__ dst) {
    int e = blockIdx.x * blockDim.x + threadIdx.x;
    if (e < NE) {
        int s = __ldg(&src[e]);
        int pos = atomicAdd(&g_cursor[__ldg(&dst[e])], 1);
        g_edge[pos] = make_int2(s, __float_as_int(g_norm_src[s]));
    }
}

// ---------------------------------------------------------------
// Layer-1 fused aggregate: warp per dst node.
// agg4 = sum_e w*nf4[src], ws = sum_e w  (reduced across lanes)
// out[dst,:] = norm_dst * (agg4 @ W_emb + ws * b_emb)
__global__ void __launch_bounds__(256)
k_spmm_l1(const float* __restrict__ nf, const float* __restrict__ Wemb,
          const float* __restrict__ bemb, float* __restrict__ out) {
    __shared__ float We[512];
    __shared__ float be[128];
    int tid = threadIdx.x;
    if (tid < 256) {
        We[tid] = Wemb[tid];
        We[tid + 256] = Wemb[tid + 256];
        if (tid < 128) be[tid] = bemb[tid];
    }
    __syncthreads();

    int gw = (blockIdx.x * blockDim.x + tid) >> 5;
    int lane = tid & 31;
    if (gw >= NN) return;
    int beg = g_row_ptr[gw];
    int end = g_row_ptr[gw + 1];
    float4 acc = make_float4(0.f, 0.f, 0.f, 0.f);
    float ws = 0.f;
    for (int j = beg + lane; j < end; j += 32) {
        int2 e = __ldg(&g_edge[j]);
        float w = __int_as_float(e.y);
        float4 v = *(const float4*)(nf + (size_t)e.x * 4);
        acc.x += w * v.x; acc.y += w * v.y;
        acc.z += w * v.z; acc.w += w * v.w;
        ws += w;
    }
    #pragma unroll
    for (int o = 16; o; o >>= 1) {
        acc.x += __shfl_xor_sync(0xffffffffu, acc.x, o);
        acc.y += __shfl_xor_sync(0xffffffffu, acc.y, o);
        acc.z += __shfl_xor_sync(0xffffffffu, acc.z, o);
        acc.w += __shfl_xor_sync(0xffffffffu, acc.w, o);
        ws    += __shfl_xor_sync(0xffffffffu, ws, o);
    }
    float nd = g_norm_dst[gw];
    float4 o4;
    int k = lane * 4;
    o4.x = nd * (acc.x * We[k+0] + acc.y * We[128+k+0] + acc.z * We[256+k+0] + acc.w * We[384+k+0] + ws * be[k+0]);
    o4.y = nd * (acc.x * We[k+1] + acc.y * We[128+k+1] + acc.z * We[256+k+1] + acc.w * We[384+k+1] + ws * be[k+1]);
    o4.z = nd * (acc.x * We[k+2] + acc.y * We[128+k+2] + acc.z * We[256+k+2] + acc.w * We[384+k+2] + ws * be[k+2]);
    o4.w = nd * (acc.x * We[k+3] + acc.y * We[128+k+3] + acc.z * We[256+k+3] + acc.w * We[384+k+3] + ws * be[k+3]);
    *(float4*)(out + (size_t)gw * EMB + k) = o4;
}

// CSR aggregation: one warp per destination node, lane owns 4 floats (float4)
__global__ void k_spmm(const float* __restrict__ h, float* __restrict__ out) {
    int gw = (blockIdx.x * blockDim.x + threadIdx.x) >> 5;
    int lane = threadIdx.x & 31;
    if (gw >= NN) return;
    int beg = g_row_ptr[gw];
    int end = g_row_ptr[gw + 1];
    float4 acc = make_float4(0.f, 0.f, 0.f, 0.f);
    int j = beg;
    for (; j + 4 <= end; j += 4) {
        int2 e0 = __ldg(&g_edge[j]);
        int2 e1 = __ldg(&g_edge[j + 1]);
        int2 e2 = __ldg(&g_edge[j + 2]);
        int2 e3 = __ldg(&g_edge[j + 3]);
        float w0 = __int_as_float(e0.y);
        float w1 = __int_as_float(e1.y);
        float w2 = __int_as_float(e2.y);
        float w3 = __int_as_float(e3.y);
        float4 v0 = *(const float4*)(h + (size_t)e0.x * EMB + lane * 4);
        float4 v1 = *(const float4*)(h + (size_t)e1.x * EMB + lane * 4);
        float4 v2 = *(const float4*)(h + (size_t)e2.x * EMB + lane * 4);
        float4 v3 = *(const float4*)(h + (size_t)e3.x * EMB + lane * 4);
        acc.x += w0 * v0.x + w1 * v1.x + w2 * v2.x + w3 * v3.x;
        acc.y += w0 * v0.y + w1 * v1.y + w2 * v2.y + w3 * v3.y;
        acc.z += w0 * v0.z + w1 * v1.z + w2 * v2.z + w3 * v3.z;
        acc.w += w0 * v0.w + w1 * v1.w + w2 * v2.w + w3 * v3.w;
    }
    for (; j < end; j++) {
        int2 e0 = __ldg(&g_edge[j]);
        float w0 = __int_as_float(e0.y);
        float4 v0 = *(const float4*)(h + (size_t)e0.x * EMB + lane * 4);
        acc.x += w0 * v0.x;
        acc.y += w0 * v0.y;
        acc.z += w0 * v0.z;
        acc.w += w0 * v0.w;
    }
    float nd = g_norm_dst[gw];
    acc.x *= nd; acc.y *= nd; acc.z *= nd; acc.w *= nd;
    *(float4*)(out + (size_t)gw * EMB + lane * 4) = acc;
}

// ---------------------------------------------------------------
__device__ __forceinline__ uint32_t f2tf32(float f) {
    uint32_t r;
    asm("cvt.rna.tf32.f32 %0, %1;" : "=r"(r) : "f"(f));
    return r;
}

// Tensor-core GEMM: C[M,128] = relu(A[M,128] @ W[128,128] + bias)
// mma.sync.m16n8k8 tf32, fp32 accumulate. 8 warps (4x2), tile 128x128, BK=64.
// dyn smem: As[64*132] | Ws[64*132] (uint32)
template <bool RELU>
__global__ void __launch_bounds__(256)
k_gemm_tc(const float* __restrict__ A, const float* __restrict__ W,
          const float* __restrict__ bias, float* __restrict__ C, int M) {
    extern __shared__ uint32_t sm[];
    uint32_t* As = sm;               // [64][132] : [k][m]
    uint32_t* Ws = sm + 64 * 132;    // [64][132] : [k][n]
    int tid  = threadIdx.x;
    int warp = tid >> 5;
    int lane = tid & 31;
    int wm = warp & 3;
    int wn = warp >> 2;
    int lg = lane >> 2;
    int lt = lane & 3;
    int row0 = blockIdx.x * 128;

    float c[2][8][4] = {};

    for (int k0 = 0; k0 < 128; k0 += 64) {
        // A tile 128x64 -> As[k][m]  (2048 float4, 8 per thread)
        #pragma unroll
        for (int it = 0; it < 8; it++) {
            int f  = tid + it * 256;
            int m  = f >> 4;                // 0..127
            int kq = (f & 15) << 2;         // 0..60
            int gr = row0 + m;
            float4 a = (gr < M) ? *(const float4*)(A + (size_t)gr * 128 + k0 + kq)
                                : make_float4(0.f, 0.f, 0.f, 0.f);
            As[(kq + 0) * 132 + m] = f2tf32(a.x);
            As[(kq + 1) * 132 + m] = f2tf32(a.y);
            As[(kq + 2) * 132 + m] = f2tf32(a.z);
            As[(kq + 3) * 132 + m] = f2tf32(a.w);
        }
        // W tile 64x128 -> Ws[k][n]
        #pragma unroll
        for (int it = 0; it < 8; it++) {
            int f = tid + it * 256;
            int k = f >> 5;                 // 0..63
            int n = (f & 31) << 2;          // 0..124
            float4 w = *(const float4*)(W + (size_t)(k0 + k) * 128 + n);
            Ws[k * 132 + n + 0] = f2tf32(w.x);
            Ws[k * 132 + n + 1] = f2tf32(w.y);
            Ws[k * 132 + n + 2] = f2tf32(w.z);
            Ws[k * 132 + n + 3] = f2tf32(w.w);
        }
        __syncthreads();

        #pragma unroll
        for (int ks = 0; ks < 64; ks += 8) {
            uint32_t af[2][4];
            #pragma unroll
            for (int mt = 0; mt < 2; mt++) {
                int m = wm * 32 + mt * 16 + lg;
                af[mt][0] = As[(ks + lt) * 132 + m];
                af[mt][1] = As[(ks + lt) * 132 + m + 8];
                af[mt][2] = As[(ks + 4 + lt) * 132 + m];
                af[mt][3] = As[(ks + 4 + lt) * 132 + m + 8];
            }
            #pragma unroll
            for (int nt = 0; nt < 8; nt++) {
                int n = wn * 64 + nt * 8 + lg;
                uint32_t b0 = Ws[(ks + lt) * 132 + n];
                uint32_t b1 = Ws[(ks + 4 + lt) * 132 + n];
                #pragma unroll
                for (int mt = 0; mt < 2; mt++) {
                    asm volatile(
                        "mma.sync.aligned.m16n8k8.row.col.f32.tf32.tf32.f32 "
                        "{%0,%1,%2,%3}, {%4,%5,%6,%7}, {%8,%9}, {%0,%1,%2,%3};"
                        : "+f"(c[mt][nt][0]), "+f"(c[mt][nt][1]),
                          "+f"(c[mt][nt][2]), "+f"(c[mt][nt][3])
                        : "r"(af[mt][0]), "r"(af[mt][1]),
                          "r"(af[mt][2]), "r"(af[mt][3]),
                          "r"(b0), "r"(b1));
                }
            }
        }
        __syncthreads();
    }

    #pragma unroll
    for (int nt = 0; nt < 8; nt++) {
        int col = wn * 64 + nt * 8 + 2 * lt;
        float2 bv = *(const float2*)(bias + col);
        #pragma unroll
        for (int mt = 0; mt < 2; mt++) {
            int r = row0 + wm * 32 + mt * 16 + lg;
            float2 o0, o1;
            o0.x = c[mt][nt][0] + bv.x;
            o0.y = c[mt][nt][1] + bv.y;
            o1.x = c[mt][nt][2] + bv.x;
            o1.y = c[mt][nt][3] + bv.y;
            if (RELU) {
                o0.x = fmaxf(o0.x, 0.f); o0.y = fmaxf(o0.y, 0.f);
                o1.x = fmaxf(o1.x, 0.f); o1.y = fmaxf(o1.y, 0.f);
            }
            if (r < M)     *(float2*)(C + (size_t)r * 128 + col)       = o0;
            if (r + 8 < M) *(float2*)(C + (size_t)(r + 8) * 128 + col) = o1;
        }
    }
}

// ---------------------------------------------------------------
// Final fused: out[r] = relu(A[r,:] @ Wo1 + b1) . w2 + b2
__global__ void __launch_bounds__(256)
k_gemm_gemv(const float* __restrict__ A, const float* __restrict__ W,
            const float* __restrict__ bias, const float* __restrict__ w2,
            const float* __restrict__ b2, float* __restrict__ out, int M) {
    __shared__ uint32_t As[32][132];
    __shared__ uint32_t Ws[32][132];
    __shared__ float red[128];
    __shared__ float w2s[128];
    int tid  = threadIdx.x;
    int warp = tid >> 5, lane = tid & 31;
    int wm = warp & 3, wn = warp >> 2;
    int lg = lane >> 2, lt = lane & 3;
    int row0 = blockIdx.x * 128;

    if (tid < 128) { red[tid] = 0.f; w2s[tid] = w2[tid]; }

    float c[2][8][4] = {};

    for (int k0 = 0; k0 < 128; k0 += 32) {
        #pragma unroll
        for (int it = 0; it < 4; it++) {
            int f  = tid + it * 256;
            int m  = f >> 3;
            int kq = (f & 7) << 2;
            int gr = row0 + m;
            float4 a = (gr < M) ? *(const float4*)(A + (size_t)gr * 128 + k0 + kq)
                                : make_float4(0.f, 0.f, 0.f, 0.f);
            As[kq + 0][m] = f2tf32(a.x);
            As[kq + 1][m] = f2tf32(a.y);
            As[kq + 2][m] = f2tf32(a.z);
            As[kq + 3][m] = f2tf32(a.w);
        }
        #pragma unroll
        for (int it = 0; it < 4; it++) {
            int f = tid + it * 256;
            int k = f >> 5;
            int n = (f & 31) << 2;
            float4 w = *(const float4*)(W + (size_t)(k0 + k) * 128 + n);
            Ws[k][n + 0] = f2tf32(w.x);
            Ws[k][n + 1] = f2tf32(w.y);
            Ws[k][n + 2] = f2tf32(w.z);
            Ws[k][n + 3] = f2tf32(w.w);
        }
        __syncthreads();

        #pragma unroll
        for (int ks = 0; ks < 32; ks += 8) {
            uint32_t af[2][4];
            #pragma unroll
            for (int mt = 0; mt < 2; mt++) {
                int m = wm * 32 + mt * 16 + lg;
                af[mt][0] = As[ks + lt][m];
                af[mt][1] = As[ks + lt][m + 8];
                af[mt][2] = As[ks + 4 + lt][m];
                af[mt][3] = As[ks + 4 + lt][m + 8];
            }
            #pragma unroll
            for (int nt = 0; nt < 8; nt++) {
                int n = wn * 64 + nt * 8 + lg;
                uint32_t b0 = Ws[ks + lt][n];
                uint32_t b1 = Ws[ks + 4 + lt][n];
                #pragma unroll
                for (int mt = 0; mt < 2; mt++) {
                    asm volatile(
                        "mma.sync.aligned.m16n8k8.row.col.f32.tf32.tf32.f32 "
                        "{%0,%1,%2,%3}, {%4,%5,%6,%7}, {%8,%9}, {%0,%1,%2,%3};"
                        : "+f"(c[mt][nt][0]), "+f"(c[mt][nt][1]),
                          "+f"(c[mt][nt][2]), "+f"(c[mt][nt][3])
                        : "r"(af[mt][0]), "r"(af[mt][1]),
                          "r"(af[mt][2]), "r"(af[mt][3]),
                          "r"(b0), "r"(b1));
                }
            }
        }
        __syncthreads();
    }

    #pragma unroll
    for (int mt = 0; mt < 2; mt++) {
        float dot0 = 0.f, dot1 = 0.f;
        #pragma unroll
        for (int nt = 0; nt < 8; nt++) {
            int col = wn * 64 + nt * 8 + 2 * lt;
            float2 bv = *(const float2*)(bias + col);
            float wa = w2s[col], wb = w2s[col + 1];
            dot0 += fmaxf(c[mt][nt][0] + bv.x, 0.f) * wa
                  + fmaxf(c[mt][nt][1] + bv.y, 0.f) * wb;
            dot1 += fmaxf(c[mt][nt][2] + bv.x, 0.f) * wa
                  + fmaxf(c[mt][nt][3] + bv.y, 0.f) * wb;
        }
        int rl = wm * 32 + mt * 16 + lg;
        atomicAdd(&red[rl], dot0);
        atomicAdd(&red[rl + 8], dot1);
    }
    __syncthreads();
    if (tid < 128 && row0 + tid < M)
        out[row0 + tid] = red[tid] + b2[0];
}

// ---------------------------------------------------------------
extern "C" void kernel_launch(void* const* d_in, const int* in_sizes, int n_in,
                              void* d_out, int out_size) {
    const float* nf   = (const float*)d_in[0];
    const int*   src  = (const int*)d_in[1];
    const int*   dst  = (const int*)d_in[2];
    const float* Wemb = (const float*)d_in[3];
    const float* bemb = (const float*)d_in[4];
    const float* Wg   = (const float*)d_in[5];
    const float* bg   = (const float*)d_in[6];
    const float* Wo1  = (const float*)d_in[7];
    const float* bo1  = (const float*)d_in[8];
    const float* Wo2  = (const float*)d_in[9];
    const float* bo2  = (const float*)d_in[10];
    float* out = (float*)d_out;

    float *hA, *hB;
    cudaGetSymbolAddress((void**)&hA, g_hA);
    cudaGetSymbolAddress((void**)&hB, g_hB);

    const int SM_GEMM = 2 * 64 * 132 * 4;   // 67584 bytes
    cudaFuncSetAttribute(k_gemm_tc<true>,
                         cudaFuncAttributeMaxDynamicSharedMemorySize, SM_GEMM);

    const int NB_EDGE = (NE + 255) / 256;
    const int NB_WARP = (NN * 32 + 255) / 256;   // warp-per-node kernels

    k_count<<<NB_EDGE, 256>>>(src, dst);                        // 0
    k_scanA<<<SCAN_BLOCKS, 256>>>();                            // 1
    k_scanB<<<SCAN_BLOCKS, 256>>>();                            // 2
    k_fill<<<NB_EDGE, 256>>>(src, dst);                         // 3

    // layer 1: fused embed+aggregate -> hB, then GEMM -> hA
    k_spmm_l1<<<NB_WARP, 256>>>(nf, Wemb, bemb, hB);            // 4
    k_gemm_tc<true><<<NB_TILE, 256, SM_GEMM>>>(hB, Wg, bg, hA, NN);   // 5

    // layers 2,3
    k_spmm<<<NB_WARP, 256>>>(hA, hB);                           // 6
    k_gemm_tc<true><<<NB_TILE, 256, SM_GEMM>>>(hB, Wg + 128 * 128,
                                               bg + 128, hA, NN);     // 7
    k_spmm<<<NB_WARP, 256>>>(hA, hB);                           // 8
    k_gemm_tc<true><<<NB_TILE, 256, SM_GEMM>>>(hB, Wg + 2 * 128 * 128,
                                               bg + 2 * 128, hA, NN); // 9

    // head: relu(hA@Wo1+b1).Wo2 + b2 -> out
    k_gemm_gemv<<<NB_TILE, 256>>>(hA, Wo1, bo1, Wo2, bo2, out, NN);   // 10
}

// round 7
// speedup vs baseline: 1.0322x; 1.0322x over previous
#include <cuda_runtime.h>
#include <cstdint>

#define NN 50000
#define NE 640000
#define EMB 128
#define SCAN_BLOCKS 196   // 196*256 = 50176 >= NN
#define NB_TILE 391       // (NN+127)/128

// ---- scratch (device globals; zero-initialized at load, re-zeroed each launch) ----
__device__ float g_hA[NN * EMB];      // 25.6 MB
__device__ float g_hB[NN * EMB];      // 25.6 MB
__device__ float g_norm_src[NN];
__device__ float g_norm_dst[NN];
__device__ int   g_deg_src[NN];       // zeroed at end of scanB each launch
__device__ int   g_deg_dst[NN];
__device__ int   g_row_ptr[NN + 1];
__device__ int   g_cursor[NN];
__device__ int2  g_edge[NE];          // (src, __float_as_int(w)) packed
__device__ int   g_part[SCAN_BLOCKS];

// ---------------------------------------------------------------
__global__ void k_count(const int* __restrict__ src, const int* __restrict__ dst) {
    int e = blockIdx.x * blockDim.x + threadIdx.x;
    if (e < NE) {
        atomicAdd(&g_deg_src[__ldg(&src[e])], 1);
        atomicAdd(&g_deg_dst[__ldg(&dst[e])], 1);
    }
}

__global__ void k_scanA() {
    __shared__ int sh[256];
    int i = blockIdx.x * 256 + threadIdx.x;
    int d = (i < NN) ? g_deg_dst[i] : 0;
    sh[threadIdx.x] = d;
    __syncthreads();
    #pragma unroll
    for (int off = 128; off; off >>= 1) {
        if (threadIdx.x < off) sh[threadIdx.x] += sh[threadIdx.x + off];
        __syncthreads();
    }
    if (threadIdx.x == 0) g_part[blockIdx.x] = sh[0];
}

__global__ void k_scanB() {
    __shared__ int sh[256];
    __shared__ int pre;
    int tid = threadIdx.x;
    int b = blockIdx.x;
    int pv = (tid < b) ? g_part[tid] : 0;
    sh[tid] = pv;
    __syncthreads();
    #pragma unroll
    for (int off = 128; off; off >>= 1) {
        if (tid < off) sh[tid] += sh[tid + off];
        __syncthreads();
    }
    if (tid == 0) pre = sh[0];
    __syncthreads();
    int prefix = pre;
    __syncthreads();

    int i = b * 256 + tid;
    int d = (i < NN) ? g_deg_dst[i] : 0;
    sh[tid] = d;
    __syncthreads();
    #pragma unroll
    for (int off = 1; off < 256; off <<= 1) {
        int v = (tid >= off) ? sh[tid - off] : 0;
        __syncthreads();
        sh[tid] += v;
        __syncthreads();
    }
    int incl = sh[tid];
    int excl = incl - d;
    if (i < NN) {
        int base = prefix + excl;
        g_row_ptr[i] = base;
        g_cursor[i]  = base;
        if (i == NN - 1) g_row_ptr[NN] = prefix + incl;
        int ds = g_deg_src[i];
        g_norm_dst[i] = rsqrtf((float)max(d, 1));
        g_norm_src[i] = rsqrtf((float)max(ds, 1));
        g_deg_dst[i] = 0;
        g_deg_src[i] = 0;
    }
}

__global__ void k_fill(const int* __restrict__ src, const int* __restrict__ dst) {
    int e = blockIdx.x * blockDim.x + threadIdx.x;
    if (e < NE) {
        int s = __ldg(&src[e]);
        int pos = atomicAdd(&g_cursor[__ldg(&dst[e])], 1);
        g_edge[pos] = make_int2(s, __float_as_int(g_norm_src[s]));
    }
}

// ---------------------------------------------------------------
// Layer-1 fused aggregate: warp per dst node.
// agg4 = sum_e w*nf4[src], ws = sum_e w  (reduced across lanes)
// out[dst,:] = norm_dst * (agg4 @ W_emb + ws * b_emb)
__global__ void __launch_bounds__(256)
k_spmm_l1(const float* __restrict__ nf, const float* __restrict__ Wemb,
          const float* __restrict__ bemb, float* __restrict__ out) {
    __shared__ float We[512];
    __shared__ float be[128];
    int tid = threadIdx.x;
    if (tid < 256) {
        We[tid] = Wemb[tid];
        We[tid + 256] = Wemb[tid + 256];
        if (tid < 128) be[tid] = bemb[tid];
    }
    __syncthreads();

    int gw = (blockIdx.x * blockDim.x + tid) >> 5;
    int lane = tid & 31;
    if (gw >= NN) return;
    int beg = g_row_ptr[gw];
    int end = g_row_ptr[gw + 1];
    float4 acc = make_float4(0.f, 0.f, 0.f, 0.f);
    float ws = 0.f;
    for (int j = beg + lane; j < end; j += 32) {
        int2 e = __ldg(&g_edge[j]);
        float w = __int_as_float(e.y);
        float4 v = *(const float4*)(nf + (size_t)e.x * 4);
        acc.x += w * v.x; acc.y += w * v.y;
        acc.z += w * v.z; acc.w += w * v.w;
        ws += w;
    }
    #pragma unroll
    for (int o = 16; o; o >>= 1) {
        acc.x += __shfl_xor_sync(0xffffffffu, acc.x, o);
        acc.y += __shfl_xor_sync(0xffffffffu, acc.y, o);
        acc.z += __shfl_xor_sync(0xffffffffu, acc.z, o);
        acc.w += __shfl_xor_sync(0xffffffffu, acc.w, o);
        ws    += __shfl_xor_sync(0xffffffffu, ws, o);
    }
    float nd = g_norm_dst[gw];
    float4 o4;
    int k = lane * 4;
    o4.x = nd * (acc.x * We[k+0] + acc.y * We[128+k+0] + acc.z * We[256+k+0] + acc.w * We[384+k+0] + ws * be[k+0]);
    o4.y = nd * (acc.x * We[k+1] + acc.y * We[128+k+1] + acc.z * We[256+k+1] + acc.w * We[384+k+1] + ws * be[k+1]);
    o4.z = nd * (acc.x * We[k+2] + acc.y * We[128+k+2] + acc.z * We[256+k+2] + acc.w * We[384+k+2] + ws * be[k+2]);
    o4.w = nd * (acc.x * We[k+3] + acc.y * We[128+k+3] + acc.z * We[256+k+3] + acc.w * We[384+k+3] + ws * be[k+3]);
    *(float4*)(out + (size_t)gw * EMB + k) = o4;
}

// CSR aggregation: one warp per destination node, lane owns 4 floats (float4)
__global__ void k_spmm(const float* __restrict__ h, float* __restrict__ out) {
    int gw = (blockIdx.x * blockDim.x + threadIdx.x) >> 5;
    int lane = threadIdx.x & 31;
    if (gw >= NN) return;
    int beg = g_row_ptr[gw];
    int end = g_row_ptr[gw + 1];
    float4 acc = make_float4(0.f, 0.f, 0.f, 0.f);
    int j = beg;
    for (; j + 4 <= end; j += 4) {
        int2 e0 = __ldg(&g_edge[j]);
        int2 e1 = __ldg(&g_edge[j + 1]);
        int2 e2 = __ldg(&g_edge[j + 2]);
        int2 e3 = __ldg(&g_edge[j + 3]);
        float w0 = __int_as_float(e0.y);
        float w1 = __int_as_float(e1.y);
        float w2 = __int_as_float(e2.y);
        float w3 = __int_as_float(e3.y);
        float4 v0 = *(const float4*)(h + (size_t)e0.x * EMB + lane * 4);
        float4 v1 = *(const float4*)(h + (size_t)e1.x * EMB + lane * 4);
        float4 v2 = *(const float4*)(h + (size_t)e2.x * EMB + lane * 4);
        float4 v3 = *(const float4*)(h + (size_t)e3.x * EMB + lane * 4);
        acc.x += w0 * v0.x + w1 * v1.x + w2 * v2.x + w3 * v3.x;
        acc.y += w0 * v0.y + w1 * v1.y + w2 * v2.y + w3 * v3.y;
        acc.z += w0 * v0.z + w1 * v1.z + w2 * v2.z + w3 * v3.z;
        acc.w += w0 * v0.w + w1 * v1.w + w2 * v2.w + w3 * v3.w;
    }
    for (; j < end; j++) {
        int2 e0 = __ldg(&g_edge[j]);
        float w0 = __int_as_float(e0.y);
        float4 v0 = *(const float4*)(h + (size_t)e0.x * EMB + lane * 4);
        acc.x += w0 * v0.x;
        acc.y += w0 * v0.y;
        acc.z += w0 * v0.z;
        acc.w += w0 * v0.w;
    }
    float nd = g_norm_dst[gw];
    acc.x *= nd; acc.y *= nd; acc.z *= nd; acc.w *= nd;
    *(float4*)(out + (size_t)gw * EMB + lane * 4) = acc;
}

// ---------------------------------------------------------------
__device__ __forceinline__ uint32_t f2tf32(float f) {
    uint32_t r;
    asm("cvt.rna.tf32.f32 %0, %1;" : "=r"(r) : "f"(f));
    return r;
}

// Tensor-core GEMM: C[M,128] = relu(A[M,128] @ W[128,128] + bias)
// mma.sync.m16n8k8 tf32, fp32 accumulate. 8 warps (4x2), tile 128x128, BK=32.
template <bool RELU>
__global__ void __launch_bounds__(256)
k_gemm_tc(const float* __restrict__ A, const float* __restrict__ W,
          const float* __restrict__ bias, float* __restrict__ C, int M) {
    __shared__ uint32_t As[32][132];
    __shared__ uint32_t Ws[32][132];
    int tid  = threadIdx.x;
    int warp = tid >> 5;
    int lane = tid & 31;
    int wm = warp & 3;
    int wn = warp >> 2;
    int lg = lane >> 2;
    int lt = lane & 3;
    int row0 = blockIdx.x * 128;

    float c[2][8][4] = {};

    for (int k0 = 0; k0 < 128; k0 += 32) {
        #pragma unroll
        for (int it = 0; it < 4; it++) {
            int f  = tid + it * 256;
            int m  = f >> 3;
            int kq = (f & 7) << 2;
            int gr = row0 + m;
            float4 a = (gr < M) ? *(const float4*)(A + (size_t)gr * 128 + k0 + kq)
                                : make_float4(0.f, 0.f, 0.f, 0.f);
            As[kq + 0][m] = f2tf32(a.x);
            As[kq + 1][m] = f2tf32(a.y);
            As[kq + 2][m] = f2tf32(a.z);
            As[kq + 3][m] = f2tf32(a.w);
        }
        #pragma unroll
        for (int it = 0; it < 4; it++) {
            int f = tid + it * 256;
            int k = f >> 5;
            int n = (f & 31) << 2;
            float4 w = *(const float4*)(W + (size_t)(k0 + k) * 128 + n);
            Ws[k][n + 0] = f2tf32(w.x);
            Ws[k][n + 1] = f2tf32(w.y);
            Ws[k][n + 2] = f2tf32(w.z);
            Ws[k][n + 3] = f2tf32(w.w);
        }
        __syncthreads();

        #pragma unroll
        for (int ks = 0; ks < 32; ks += 8) {
            uint32_t af[2][4];
            #pragma unroll
            for (int mt = 0; mt < 2; mt++) {
                int m = wm * 32 + mt * 16 + lg;
                af[mt][0] = As[ks + lt][m];
                af[mt][1] = As[ks + lt][m + 8];
                af[mt][2] = As[ks + 4 + lt][m];
                af[mt][3] = As[ks + 4 + lt][m + 8];
            }
            #pragma unroll
            for (int nt = 0; nt < 8; nt++) {
                int n = wn * 64 + nt * 8 + lg;
                uint32_t b0 = Ws[ks + lt][n];
                uint32_t b1 = Ws[ks + 4 + lt][n];
                #pragma unroll
                for (int mt = 0; mt < 2; mt++) {
                    asm volatile(
                        "mma.sync.aligned.m16n8k8.row.col.f32.tf32.tf32.f32 "
                        "{%0,%1,%2,%3}, {%4,%5,%6,%7}, {%8,%9}, {%0,%1,%2,%3};"
                        : "+f"(c[mt][nt][0]), "+f"(c[mt][nt][1]),
                          "+f"(c[mt][nt][2]), "+f"(c[mt][nt][3])
                        : "r"(af[mt][0]), "r"(af[mt][1]),
                          "r"(af[mt][2]), "r"(af[mt][3]),
                          "r"(b0), "r"(b1));
                }
            }
        }
        __syncthreads();
    }

    #pragma unroll
    for (int nt = 0; nt < 8; nt++) {
        int col = wn * 64 + nt * 8 + 2 * lt;
        float2 bv = *(const float2*)(bias + col);
        #pragma unroll
        for (int mt = 0; mt < 2; mt++) {
            int r = row0 + wm * 32 + mt * 16 + lg;
            float2 o0, o1;
            o0.x = c[mt][nt][0] + bv.x;
            o0.y = c[mt][nt][1] + bv.y;
            o1.x = c[mt][nt][2] + bv.x;
            o1.y = c[mt][nt][3] + bv.y;
            if (RELU) {
                o0.x = fmaxf(o0.x, 0.f); o0.y = fmaxf(o0.y, 0.f);
                o1.x = fmaxf(o1.x, 0.f); o1.y = fmaxf(o1.y, 0.f);
            }
            if (r < M)     *(float2*)(C + (size_t)r * 128 + col)       = o0;
            if (r + 8 < M) *(float2*)(C + (size_t)(r + 8) * 128 + col) = o1;
        }
    }
}

// ---------------------------------------------------------------
// Final fused: out[r] = relu(A[r,:] @ Wo1 + b1) . w2 + b2
__global__ void __launch_bounds__(256)
k_gemm_gemv(const float* __restrict__ A, const float* __restrict__ W,
            const float* __restrict__ bias, const float* __restrict__ w2,
            const float* __restrict__ b2, float* __restrict__ out, int M) {
    __shared__ uint32_t As[32][132];
    __shared__ uint32_t Ws[32][132];
    __shared__ float red[128];
    __shared__ float w2s[128];
    int tid  = threadIdx.x;
    int warp = tid >> 5, lane = tid & 31;
    int wm = warp & 3, wn = warp >> 2;
    int lg = lane >> 2, lt = lane & 3;
    int row0 = blockIdx.x * 128;

    if (tid < 128) { red[tid] = 0.f; w2s[tid] = w2[tid]; }

    float c[2][8][4] = {};

    for (int k0 = 0; k0 < 128; k0 += 32) {
        #pragma unroll
        for (int it = 0; it < 4; it++) {
            int f  = tid + it * 256;
            int m  = f >> 3;
            int kq = (f & 7) << 2;
            int gr = row0 + m;
            float4 a = (gr < M) ? *(const float4*)(A + (size_t)gr * 128 + k0 + kq)
                                : make_float4(0.f, 0.f, 0.f, 0.f);
            As[kq + 0][m] = f2tf32(a.x);
            As[kq + 1][m] = f2tf32(a.y);
            As[kq + 2][m] = f2tf32(a.z);
            As[kq + 3][m] = f2tf32(a.w);
        }
        #pragma unroll
        for (int it = 0; it < 4; it++) {
            int f = tid + it * 256;
            int k = f >> 5;
            int n = (f & 31) << 2;
            float4 w = *(const float4*)(W + (size_t)(k0 + k) * 128 + n);
            Ws[k][n + 0] = f2tf32(w.x);
            Ws[k][n + 1] = f2tf32(w.y);
            Ws[k][n + 2] = f2tf32(w.z);
            Ws[k][n + 3] = f2tf32(w.w);
        }
        __syncthreads();

        #pragma unroll
        for (int ks = 0; ks < 32; ks += 8) {
            uint32_t af[2][4];
            #pragma unroll
            for (int mt = 0; mt < 2; mt++) {
                int m = wm * 32 + mt * 16 + lg;
                af[mt][0] = As[ks + lt][m];
                af[mt][1] = As[ks + lt][m + 8];
                af[mt][2] = As[ks + 4 + lt][m];
                af[mt][3] = As[ks + 4 + lt][m + 8];
            }
            #pragma unroll
            for (int nt = 0; nt < 8; nt++) {
                int n = wn * 64 + nt * 8 + lg;
                uint32_t b0 = Ws[ks + lt][n];
                uint32_t b1 = Ws[ks + 4 + lt][n];
                #pragma unroll
                for (int mt = 0; mt < 2; mt++) {
                    asm volatile(
                        "mma.sync.aligned.m16n8k8.row.col.f32.tf32.tf32.f32 "
                        "{%0,%1,%2,%3}, {%4,%5,%6,%7}, {%8,%9}, {%0,%1,%2,%3};"
                        : "+f"(c[mt][nt][0]), "+f"(c[mt][nt][1]),
                          "+f"(c[mt][nt][2]), "+f"(c[mt][nt][3])
                        : "r"(af[mt][0]), "r"(af[mt][1]),
                          "r"(af[mt][2]), "r"(af[mt][3]),
                          "r"(b0), "r"(b1));
                }
            }
        }
        __syncthreads();
    }

    #pragma unroll
    for (int mt = 0; mt < 2; mt++) {
        float dot0 = 0.f, dot1 = 0.f;
        #pragma unroll
        for (int nt = 0; nt < 8; nt++) {
            int col = wn * 64 + nt * 8 + 2 * lt;
            float2 bv = *(const float2*)(bias + col);
            float wa = w2s[col], wb = w2s[col + 1];
            dot0 += fmaxf(c[mt][nt][0] + bv.x, 0.f) * wa
                  + fmaxf(c[mt][nt][1] + bv.y, 0.f) * wb;
            dot1 += fmaxf(c[mt][nt][2] + bv.x, 0.f) * wa
                  + fmaxf(c[mt][nt][3] + bv.y, 0.f) * wb;
        }
        int rl = wm * 32 + mt * 16 + lg;
        atomicAdd(&red[rl], dot0);
        atomicAdd(&red[rl + 8], dot1);
    }
    __syncthreads();
    if (tid < 128 && row0 + tid < M)
        out[row0 + tid] = red[tid] + b2[0];
}

// ---------------------------------------------------------------
extern "C" void kernel_launch(void* const* d_in, const int* in_sizes, int n_in,
                              void* d_out, int out_size) {
    const float* nf   = (const float*)d_in[0];
    const int*   src  = (const int*)d_in[1];
    const int*   dst  = (const int*)d_in[2];
    const float* Wemb = (const float*)d_in[3];
    const float* bemb = (const float*)d_in[4];
    const float* Wg   = (const float*)d_in[5];
    const float* bg   = (const float*)d_in[6];
    const float* Wo1  = (const float*)d_in[7];
    const float* bo1  = (const float*)d_in[8];
    const float* Wo2  = (const float*)d_in[9];
    const float* bo2  = (const float*)d_in[10];
    float* out = (float*)d_out;

    float *hA, *hB;
    cudaGetSymbolAddress((void**)&hA, g_hA);
    cudaGetSymbolAddress((void**)&hB, g_hB);

    const int NB_EDGE = (NE + 255) / 256;
    const int NB_WARP = (NN * 32 + 255) / 256;   // warp-per-node kernels

    k_count<<<NB_EDGE, 256>>>(src, dst);                        // 0
    k_scanA<<<SCAN_BLOCKS, 256>>>();                            // 1
    k_scanB<<<SCAN_BLOCKS, 256>>>();                            // 2
    k_fill<<<NB_EDGE, 256>>>(src, dst);                         // 3

    // layer 1: fused embed+aggregate -> hB, then GEMM -> hA
    k_spmm_l1<<<NB_WARP, 256>>>(nf, Wemb, bemb, hB);            // 4
    k_gemm_tc<true><<<NB_TILE, 256>>>(hB, Wg, bg, hA, NN);      // 5

    // layers 2,3
    k_spmm<<<NB_WARP, 256>>>(hA, hB);                           // 6
    k_gemm_tc<true><<<NB_TILE, 256>>>(hB, Wg + 128 * 128,
                                      bg + 128, hA, NN);        // 7
    k_spmm<<<NB_WARP, 256>>>(hA, hB);                           // 8
    k_gemm_tc<true><<<NB_TILE, 256>>>(hB, Wg + 2 * 128 * 128,
                                      bg + 2 * 128, hA, NN);    // 9

    // head: relu(hA@Wo1+b1).Wo2 + b2 -> out
    k_gemm_gemv<<<NB_TILE, 256>>>(hA, Wo1, bo1, Wo2, bo2, out, NN);   // 10
}

// round 8
// speedup vs baseline: 1.1205x; 1.0855x over previous
#include <cuda_runtime.h>
#include <cuda_fp16.h>
#include <cstdint>

#define NN 50000
#define NE 640000
#define EMB 128
#define SCAN_BLOCKS 196   // 196*256 = 50176 >= NN
#define NB_TILE 391       // (NN+127)/128

// ---- scratch (device globals; zero-initialized at load, re-zeroed each launch) ----
__device__ float  g_agg[NN * EMB];    // fp32 spmm output / gemm input (25.6 MB)
__device__ __half g_h16[NN * EMB];    // fp16 gemm output / spmm gather input (12.8 MB)
__device__ float g_norm_src[NN];
__device__ float g_norm_dst[NN];
__device__ int   g_deg_src[NN];       // zeroed at end of scanB each launch
__device__ int   g_deg_dst[NN];
__device__ int   g_row_ptr[NN + 1];
__device__ int   g_cursor[NN];
__device__ int2  g_edge[NE];          // (src, __float_as_int(w)) packed
__device__ int   g_part[SCAN_BLOCKS];

// ---------------------------------------------------------------
__global__ void k_count(const int* __restrict__ src, const int* __restrict__ dst) {
    int e = blockIdx.x * blockDim.x + threadIdx.x;
    if (e < NE) {
        atomicAdd(&g_deg_src[__ldg(&src[e])], 1);
        atomicAdd(&g_deg_dst[__ldg(&dst[e])], 1);
    }
}

__global__ void k_scanA() {
    __shared__ int sh[256];
    int i = blockIdx.x * 256 + threadIdx.x;
    int d = (i < NN) ? g_deg_dst[i] : 0;
    sh[threadIdx.x] = d;
    __syncthreads();
    #pragma unroll
    for (int off = 128; off; off >>= 1) {
        if (threadIdx.x < off) sh[threadIdx.x] += sh[threadIdx.x + off];
        __syncthreads();
    }
    if (threadIdx.x == 0) g_part[blockIdx.x] = sh[0];
}

__global__ void k_scanB() {
    __shared__ int sh[256];
    __shared__ int pre;
    int tid = threadIdx.x;
    int b = blockIdx.x;
    int pv = (tid < b) ? g_part[tid] : 0;
    sh[tid] = pv;
    __syncthreads();
    #pragma unroll
    for (int off = 128; off; off >>= 1) {
        if (tid < off) sh[tid] += sh[tid + off];
        __syncthreads();
    }
    if (tid == 0) pre = sh[0];
    __syncthreads();
    int prefix = pre;
    __syncthreads();

    int i = b * 256 + tid;
    int d = (i < NN) ? g_deg_dst[i] : 0;
    sh[tid] = d;
    __syncthreads();
    #pragma unroll
    for (int off = 1; off < 256; off <<= 1) {
        int v = (tid >= off) ? sh[tid - off] : 0;
        __syncthreads();
        sh[tid] += v;
        __syncthreads();
    }
    int incl = sh[tid];
    int excl = incl - d;
    if (i < NN) {
        int base = prefix + excl;
        g_row_ptr[i] = base;
        g_cursor[i]  = base;
        if (i == NN - 1) g_row_ptr[NN] = prefix + incl;
        int ds = g_deg_src[i];
        g_norm_dst[i] = rsqrtf((float)max(d, 1));
        g_norm_src[i] = rsqrtf((float)max(ds, 1));
        g_deg_dst[i] = 0;
        g_deg_src[i] = 0;
    }
}

__global__ void k_fill(const int* __restrict__ src, const int* __restrict__ dst) {
    int e = blockIdx.x * blockDim.x + threadIdx.x;
    if (e < NE) {
        int s = __ldg(&src[e]);
        int pos = atomicAdd(&g_cursor[__ldg(&dst[e])], 1);
        g_edge[pos] = make_int2(s, __float_as_int(g_norm_src[s]));
    }
}

// ---------------------------------------------------------------
// Layer-1 fused aggregate: warp per dst node. writes fp32 agg.
__global__ void __launch_bounds__(256)
k_spmm_l1(const float* __restrict__ nf, const float* __restrict__ Wemb,
          const float* __restrict__ bemb, float* __restrict__ out) {
    __shared__ float We[512];
    __shared__ float be[128];
    int tid = threadIdx.x;
    if (tid < 256) {
        We[tid] = Wemb[tid];
        We[tid + 256] = Wemb[tid + 256];
        if (tid < 128) be[tid] = bemb[tid];
    }
    __syncthreads();

    int gw = (blockIdx.x * blockDim.x + tid) >> 5;
    int lane = tid & 31;
    if (gw >= NN) return;
    int beg = g_row_ptr[gw];
    int end = g_row_ptr[gw + 1];
    float4 acc = make_float4(0.f, 0.f, 0.f, 0.f);
    float ws = 0.f;
    for (int j = beg + lane; j < end; j += 32) {
        int2 e = __ldg(&g_edge[j]);
        float w = __int_as_float(e.y);
        float4 v = *(const float4*)(nf + (size_t)e.x * 4);
        acc.x += w * v.x; acc.y += w * v.y;
        acc.z += w * v.z; acc.w += w * v.w;
        ws += w;
    }
    #pragma unroll
    for (int o = 16; o; o >>= 1) {
        acc.x += __shfl_xor_sync(0xffffffffu, acc.x, o);
        acc.y += __shfl_xor_sync(0xffffffffu, acc.y, o);
        acc.z += __shfl_xor_sync(0xffffffffu, acc.z, o);
        acc.w += __shfl_xor_sync(0xffffffffu, acc.w, o);
        ws    += __shfl_xor_sync(0xffffffffu, ws, o);
    }
    float nd = g_norm_dst[gw];
    float4 o4;
    int k = lane * 4;
    o4.x = nd * (acc.x * We[k+0] + acc.y * We[128+k+0] + acc.z * We[256+k+0] + acc.w * We[384+k+0] + ws * be[k+0]);
    o4.y = nd * (acc.x * We[k+1] + acc.y * We[128+k+1] + acc.z * We[256+k+1] + acc.w * We[384+k+1] + ws * be[k+1]);
    o4.z = nd * (acc.x * We[k+2] + acc.y * We[128+k+2] + acc.z * We[256+k+2] + acc.w * We[384+k+2] + ws * be[k+2]);
    o4.w = nd * (acc.x * We[k+3] + acc.y * We[128+k+3] + acc.z * We[256+k+3] + acc.w * We[384+k+3] + ws * be[k+3]);
    *(float4*)(out + (size_t)gw * EMB + k) = o4;
}

// CSR aggregation over fp16 h: warp per dst node, lane owns 4 cols (uint2 = 4 halves)
__global__ void k_spmm16(const __half* __restrict__ h, float* __restrict__ out) {
    int gw = (blockIdx.x * blockDim.x + threadIdx.x) >> 5;
    int lane = threadIdx.x & 31;
    if (gw >= NN) return;
    int beg = g_row_ptr[gw];
    int end = g_row_ptr[gw + 1];
    float4 acc = make_float4(0.f, 0.f, 0.f, 0.f);
    int j = beg;
    for (; j + 4 <= end; j += 4) {
        int2 e0 = __ldg(&g_edge[j]);
        int2 e1 = __ldg(&g_edge[j + 1]);
        int2 e2 = __ldg(&g_edge[j + 2]);
        int2 e3 = __ldg(&g_edge[j + 3]);
        uint2 r0 = __ldg((const uint2*)(h + (size_t)e0.x * EMB + lane * 4));
        uint2 r1 = __ldg((const uint2*)(h + (size_t)e1.x * EMB + lane * 4));
        uint2 r2 = __ldg((const uint2*)(h + (size_t)e2.x * EMB + lane * 4));
        uint2 r3 = __ldg((const uint2*)(h + (size_t)e3.x * EMB + lane * 4));
        float w0 = __int_as_float(e0.y);
        float w1 = __int_as_float(e1.y);
        float w2 = __int_as_float(e2.y);
        float w3 = __int_as_float(e3.y);
        float2 a0 = __half22float2(*(const __half2*)&r0.x);
        float2 b0 = __half22float2(*(const __half2*)&r0.y);
        float2 a1 = __half22float2(*(const __half2*)&r1.x);
        float2 b1 = __half22float2(*(const __half2*)&r1.y);
        float2 a2 = __half22float2(*(const __half2*)&r2.x);
        float2 b2 = __half22float2(*(const __half2*)&r2.y);
        float2 a3 = __half22float2(*(const __half2*)&r3.x);
        float2 b3 = __half22float2(*(const __half2*)&r3.y);
        acc.x += w0 * a0.x + w1 * a1.x + w2 * a2.x + w3 * a3.x;
        acc.y += w0 * a0.y + w1 * a1.y + w2 * a2.y + w3 * a3.y;
        acc.z += w0 * b0.x + w1 * b1.x + w2 * b2.x + w3 * b3.x;
        acc.w += w0 * b0.y + w1 * b1.y + w2 * b2.y + w3 * b3.y;
    }
    for (; j < end; j++) {
        int2 e0 = __ldg(&g_edge[j]);
        float w0 = __int_as_float(e0.y);
        uint2 r0 = __ldg((const uint2*)(h + (size_t)e0.x * EMB + lane * 4));
        float2 a0 = __half22float2(*(const __half2*)&r0.x);
        float2 b0 = __half22float2(*(const __half2*)&r0.y);
        acc.x += w0 * a0.x;
        acc.y += w0 * a0.y;
        acc.z += w0 * b0.x;
        acc.w += w0 * b0.y;
    }
    float nd = g_norm_dst[gw];
    acc.x *= nd; acc.y *= nd; acc.z *= nd; acc.w *= nd;
    *(float4*)(out + (size_t)gw * EMB + lane * 4) = acc;
}

// ---------------------------------------------------------------
__device__ __forceinline__ uint32_t f2tf32(float f) {
    uint32_t r;
    asm("cvt.rna.tf32.f32 %0, %1;" : "=r"(r) : "f"(f));
    return r;
}

// Tensor-core GEMM: C16[M,128] = relu(A[M,128] @ W[128,128] + bias), fp16 output.
// mma.sync.m16n8k8 tf32, fp32 accumulate. 8 warps (4x2), tile 128x128, BK=32.
__global__ void __launch_bounds__(256)
k_gemm_tc16(const float* __restrict__ A, const float* __restrict__ W,
            const float* __restrict__ bias, __half* __restrict__ C, int M) {
    __shared__ uint32_t As[32][132];
    __shared__ uint32_t Ws[32][132];
    int tid  = threadIdx.x;
    int warp = tid >> 5;
    int lane = tid & 31;
    int wm = warp & 3;
    int wn = warp >> 2;
    int lg = lane >> 2;
    int lt = lane & 3;
    int row0 = blockIdx.x * 128;

    float c[2][8][4] = {};

    for (int k0 = 0; k0 < 128; k0 += 32) {
        #pragma unroll
        for (int it = 0; it < 4; it++) {
            int f  = tid + it * 256;
            int m  = f >> 3;
            int kq = (f & 7) << 2;
            int gr = row0 + m;
            float4 a = (gr < M) ? *(const float4*)(A + (size_t)gr * 128 + k0 + kq)
                                : make_float4(0.f, 0.f, 0.f, 0.f);
            As[kq + 0][m] = f2tf32(a.x);
            As[kq + 1][m] = f2tf32(a.y);
            As[kq + 2][m] = f2tf32(a.z);
            As[kq + 3][m] = f2tf32(a.w);
        }
        #pragma unroll
        for (int it = 0; it < 4; it++) {
            int f = tid + it * 256;
            int k = f >> 5;
            int n = (f & 31) << 2;
            float4 w = *(const float4*)(W + (size_t)(k0 + k) * 128 + n);
            Ws[k][n + 0] = f2tf32(w.x);
            Ws[k][n + 1] = f2tf32(w.y);
            Ws[k][n + 2] = f2tf32(w.z);
            Ws[k][n + 3] = f2tf32(w.w);
        }
        __syncthreads();

        #pragma unroll
        for (int ks = 0; ks < 32; ks += 8) {
            uint32_t af[2][4];
            #pragma unroll
            for (int mt = 0; mt < 2; mt++) {
                int m = wm * 32 + mt * 16 + lg;
                af[mt][0] = As[ks + lt][m];
                af[mt][1] = As[ks + lt][m + 8];
                af[mt][2] = As[ks + 4 + lt][m];
                af[mt][3] = As[ks + 4 + lt][m + 8];
            }
            #pragma unroll
            for (int nt = 0; nt < 8; nt++) {
                int n = wn * 64 + nt * 8 + lg;
                uint32_t b0 = Ws[ks + lt][n];
                uint32_t b1 = Ws[ks + 4 + lt][n];
                #pragma unroll
                for (int mt = 0; mt < 2; mt++) {
                    asm volatile(
                        "mma.sync.aligned.m16n8k8.row.col.f32.tf32.tf32.f32 "
                        "{%0,%1,%2,%3}, {%4,%5,%6,%7}, {%8,%9}, {%0,%1,%2,%3};"
                        : "+f"(c[mt][nt][0]), "+f"(c[mt][nt][1]),
                          "+f"(c[mt][nt][2]), "+f"(c[mt][nt][3])
                        : "r"(af[mt][0]), "r"(af[mt][1]),
                          "r"(af[mt][2]), "r"(af[mt][3]),
                          "r"(b0), "r"(b1));
                }
            }
        }
        __syncthreads();
    }

    #pragma unroll
    for (int nt = 0; nt < 8; nt++) {
        int col = wn * 64 + nt * 8 + 2 * lt;
        float2 bv = *(const float2*)(bias + col);
        #pragma unroll
        for (int mt = 0; mt < 2; mt++) {
            int r = row0 + wm * 32 + mt * 16 + lg;
            float2 o0, o1;
            o0.x = fmaxf(c[mt][nt][0] + bv.x, 0.f);
            o0.y = fmaxf(c[mt][nt][1] + bv.y, 0.f);
            o1.x = fmaxf(c[mt][nt][2] + bv.x, 0.f);
            o1.y = fmaxf(c[mt][nt][3] + bv.y, 0.f);
            if (r < M)     *(__half2*)(C + (size_t)r * 128 + col)       = __float22half2_rn(o0);
            if (r + 8 < M) *(__half2*)(C + (size_t)(r + 8) * 128 + col) = __float22half2_rn(o1);
        }
    }
}

// ---------------------------------------------------------------
// Final fused: out[r] = relu(A16[r,:] @ Wo1 + b1) . w2 + b2  (A is fp16)
__global__ void __launch_bounds__(256)
k_gemm_gemv16(const __half* __restrict__ A, const float* __restrict__ W,
              const float* __restrict__ bias, const float* __restrict__ w2,
              const float* __restrict__ b2, float* __restrict__ out, int M) {
    __shared__ uint32_t As[32][132];
    __shared__ uint32_t Ws[32][132];
    __shared__ float red[128];
    __shared__ float w2s[128];
    int tid  = threadIdx.x;
    int warp = tid >> 5, lane = tid & 31;
    int wm = warp & 3, wn = warp >> 2;
    int lg = lane >> 2, lt = lane & 3;
    int row0 = blockIdx.x * 128;

    if (tid < 128) { red[tid] = 0.f; w2s[tid] = w2[tid]; }

    float c[2][8][4] = {};

    for (int k0 = 0; k0 < 128; k0 += 32) {
        #pragma unroll
        for (int it = 0; it < 4; it++) {
            int f  = tid + it * 256;
            int m  = f >> 3;
            int kq = (f & 7) << 2;
            int gr = row0 + m;
            uint2 raw = make_uint2(0u, 0u);
            if (gr < M) raw = *(const uint2*)(A + (size_t)gr * 128 + k0 + kq);
            float2 a01 = __half22float2(*(const __half2*)&raw.x);
            float2 a23 = __half22float2(*(const __half2*)&raw.y);
            // fp16 -> tf32 is exact (same mantissa width)
            As[kq + 0][m] = __float_as_uint(a01.x);
            As[kq + 1][m] = __float_as_uint(a01.y);
            As[kq + 2][m] = __float_as_uint(a23.x);
            As[kq + 3][m] = __float_as_uint(a23.y);
        }
        #pragma unroll
        for (int it = 0; it < 4; it++) {
            int f = tid + it * 256;
            int k = f >> 5;
            int n = (f & 31) << 2;
            float4 w = *(const float4*)(W + (size_t)(k0 + k) * 128 + n);
            Ws[k][n + 0] = f2tf32(w.x);
            Ws[k][n + 1] = f2tf32(w.y);
            Ws[k][n + 2] = f2tf32(w.z);
            Ws[k][n + 3] = f2tf32(w.w);
        }
        __syncthreads();

        #pragma unroll
        for (int ks = 0; ks < 32; ks += 8) {
            uint32_t af[2][4];
            #pragma unroll
            for (int mt = 0; mt < 2; mt++) {
                int m = wm * 32 + mt * 16 + lg;
                af[mt][0] = As[ks + lt][m];
                af[mt][1] = As[ks + lt][m + 8];
                af[mt][2] = As[ks + 4 + lt][m];
                af[mt][3] = As[ks + 4 + lt][m + 8];
            }
            #pragma unroll
            for (int nt = 0; nt < 8; nt++) {
                int n = wn * 64 + nt * 8 + lg;
                uint32_t b0 = Ws[ks + lt][n];
                uint32_t b1 = Ws[ks + 4 + lt][n];
                #pragma unroll
                for (int mt = 0; mt < 2; mt++) {
                    asm volatile(
                        "mma.sync.aligned.m16n8k8.row.col.f32.tf32.tf32.f32 "
                        "{%0,%1,%2,%3}, {%4,%5,%6,%7}, {%8,%9}, {%0,%1,%2,%3};"
                        : "+f"(c[mt][nt][0]), "+f"(c[mt][nt][1]),
                          "+f"(c[mt][nt][2]), "+f"(c[mt][nt][3])
                        : "r"(af[mt][0]), "r"(af[mt][1]),
                          "r"(af[mt][2]), "r"(af[mt][3]),
                          "r"(b0), "r"(b1));
                }
            }
        }
        __syncthreads();
    }

    #pragma unroll
    for (int mt = 0; mt < 2; mt++) {
        float dot0 = 0.f, dot1 = 0.f;
        #pragma unroll
        for (int nt = 0; nt < 8; nt++) {
            int col = wn * 64 + nt * 8 + 2 * lt;
            float2 bv = *(const float2*)(bias + col);
            float wa = w2s[col], wb = w2s[col + 1];
            dot0 += fmaxf(c[mt][nt][0] + bv.x, 0.f) * wa
                  + fmaxf(c[mt][nt][1] + bv.y, 0.f) * wb;
            dot1 += fmaxf(c[mt][nt][2] + bv.x, 0.f) * wa
                  + fmaxf(c[mt][nt][3] + bv.y, 0.f) * wb;
        }
        int rl = wm * 32 + mt * 16 + lg;
        atomicAdd(&red[rl], dot0);
        atomicAdd(&red[rl + 8], dot1);
    }
    __syncthreads();
    if (tid < 128 && row0 + tid < M)
        out[row0 + tid] = red[tid] + b2[0];
}

// ---------------------------------------------------------------
extern "C" void kernel_launch(void* const* d_in, const int* in_sizes, int n_in,
                              void* d_out, int out_size) {
    const float* nf   = (const float*)d_in[0];
    const int*   src  = (const int*)d_in[1];
    const int*   dst  = (const int*)d_in[2];
    const float* Wemb = (const float*)d_in[3];
    const float* bemb = (const float*)d_in[4];
    const float* Wg   = (const float*)d_in[5];
    const float* bg   = (const float*)d_in[6];
    const float* Wo1  = (const float*)d_in[7];
    const float* bo1  = (const float*)d_in[8];
    const float* Wo2  = (const float*)d_in[9];
    const float* bo2  = (const float*)d_in[10];
    float* out = (float*)d_out;

    float*  agg;
    __half* h16;
    cudaGetSymbolAddress((void**)&agg, g_agg);
    cudaGetSymbolAddress((void**)&h16, g_h16);

    const int NB_EDGE = (NE + 255) / 256;
    const int NB_WARP = (NN * 32 + 255) / 256;   // warp-per-node kernels

    k_count<<<NB_EDGE, 256>>>(src, dst);                        // 0
    k_scanA<<<SCAN_BLOCKS, 256>>>();                            // 1
    k_scanB<<<SCAN_BLOCKS, 256>>>();                            // 2
    k_fill<<<NB_EDGE, 256>>>(src, dst);                         // 3

    // layer 1: fused embed+aggregate -> agg, then GEMM -> h16
    k_spmm_l1<<<NB_WARP, 256>>>(nf, Wemb, bemb, agg);           // 4
    k_gemm_tc16<<<NB_TILE, 256>>>(agg, Wg, bg, h16, NN);        // 5

    // layers 2,3
    k_spmm16<<<NB_WARP, 256>>>(h16, agg);                       // 6
    k_gemm_tc16<<<NB_TILE, 256>>>(agg, Wg + 128 * 128,
                                  bg + 128, h16, NN);           // 7
    k_spmm16<<<NB_WARP, 256>>>(h16, agg);                       // 8
    k_gemm_tc16<<<NB_TILE, 256>>>(agg, Wg + 2 * 128 * 128,
                                  bg + 2 * 128, h16, NN);       // 9

    // head: relu(h16@Wo1+b1).Wo2 + b2 -> out
    k_gemm_gemv16<<<NB_TILE, 256>>>(h16, Wo1, bo1, Wo2, bo2, out, NN);  // 10
}

// round 9
// speedup vs baseline: 1.1475x; 1.0241x over previous
#include <cuda_runtime.h>
#include <cuda_fp16.h>
#include <cstdint>

#define NN 50000
#define NE 640000
#define EMB 128
#define SCAN_BLOCKS 196   // 196*256 = 50176 >= NN
#define NB_TILE 391       // (NN+127)/128

// ---- scratch (device globals; zero-initialized at load, re-zeroed each launch) ----
__device__ __half g_agg[NN * EMB];    // fp16 spmm output / gemm input (12.8 MB)
__device__ __half g_h16[NN * EMB];    // fp16 gemm output / spmm gather input (12.8 MB)
__device__ float g_norm_src[NN];
__device__ float g_norm_dst[NN];
__device__ int   g_deg_src[NN];       // zeroed at end of scanB each launch
__device__ int   g_deg_dst[NN];
__device__ int   g_row_ptr[NN + 1];
__device__ int   g_cursor[NN];
__device__ int2  g_edge[NE];          // (src, __float_as_int(w)) packed
__device__ int   g_part[SCAN_BLOCKS];

// ---------------------------------------------------------------
__global__ void k_count(const int* __restrict__ src, const int* __restrict__ dst) {
    int e = blockIdx.x * blockDim.x + threadIdx.x;
    if (e < NE) {
        atomicAdd(&g_deg_src[__ldg(&src[e])], 1);
        atomicAdd(&g_deg_dst[__ldg(&dst[e])], 1);
    }
}

__global__ void k_scanA() {
    __shared__ int sh[256];
    int i = blockIdx.x * 256 + threadIdx.x;
    int d = (i < NN) ? g_deg_dst[i] : 0;
    sh[threadIdx.x] = d;
    __syncthreads();
    #pragma unroll
    for (int off = 128; off; off >>= 1) {
        if (threadIdx.x < off) sh[threadIdx.x] += sh[threadIdx.x + off];
        __syncthreads();
    }
    if (threadIdx.x == 0) g_part[blockIdx.x] = sh[0];
}

__global__ void k_scanB() {
    __shared__ int sh[256];
    __shared__ int pre;
    int tid = threadIdx.x;
    int b = blockIdx.x;
    int pv = (tid < b) ? g_part[tid] : 0;
    sh[tid] = pv;
    __syncthreads();
    #pragma unroll
    for (int off = 128; off; off >>= 1) {
        if (tid < off) sh[tid] += sh[tid + off];
        __syncthreads();
    }
    if (tid == 0) pre = sh[0];
    __syncthreads();
    int prefix = pre;
    __syncthreads();

    int i = b * 256 + tid;
    int d = (i < NN) ? g_deg_dst[i] : 0;
    sh[tid] = d;
    __syncthreads();
    #pragma unroll
    for (int off = 1; off < 256; off <<= 1) {
        int v = (tid >= off) ? sh[tid - off] : 0;
        __syncthreads();
        sh[tid] += v;
        __syncthreads();
    }
    int incl = sh[tid];
    int excl = incl - d;
    if (i < NN) {
        int base = prefix + excl;
        g_row_ptr[i] = base;
        g_cursor[i]  = base;
        if (i == NN - 1) g_row_ptr[NN] = prefix + incl;
        int ds = g_deg_src[i];
        g_norm_dst[i] = rsqrtf((float)max(d, 1));
        g_norm_src[i] = rsqrtf((float)max(ds, 1));
        g_deg_dst[i] = 0;
        g_deg_src[i] = 0;
    }
}

__global__ void k_fill(const int* __restrict__ src, const int* __restrict__ dst) {
    int e = blockIdx.x * blockDim.x + threadIdx.x;
    if (e < NE) {
        int s = __ldg(&src[e]);
        int pos = atomicAdd(&g_cursor[__ldg(&dst[e])], 1);
        g_edge[pos] = make_int2(s, __float_as_int(g_norm_src[s]));
    }
}

// ---------------------------------------------------------------
__device__ __forceinline__ uint2 pack_half4(float4 v) {
    __half2 lo = __float22half2_rn(make_float2(v.x, v.y));
    __half2 hi = __float22half2_rn(make_float2(v.z, v.w));
    uint2 r;
    r.x = *(uint32_t*)&lo;
    r.y = *(uint32_t*)&hi;
    return r;
}

// Layer-1 fused aggregate: warp per dst node. writes fp16 agg.
__global__ void __launch_bounds__(256)
k_spmm_l1(const float* __restrict__ nf, const float* __restrict__ Wemb,
          const float* __restrict__ bemb, __half* __restrict__ out) {
    __shared__ float We[512];
    __shared__ float be[128];
    int tid = threadIdx.x;
    if (tid < 256) {
        We[tid] = Wemb[tid];
        We[tid + 256] = Wemb[tid + 256];
        if (tid < 128) be[tid] = bemb[tid];
    }
    __syncthreads();

    int gw = (blockIdx.x * blockDim.x + tid) >> 5;
    int lane = tid & 31;
    if (gw >= NN) return;
    int beg = g_row_ptr[gw];
    int end = g_row_ptr[gw + 1];
    float4 acc = make_float4(0.f, 0.f, 0.f, 0.f);
    float ws = 0.f;
    for (int j = beg + lane; j < end; j += 32) {
        int2 e = __ldg(&g_edge[j]);
        float w = __int_as_float(e.y);
        float4 v = *(const float4*)(nf + (size_t)e.x * 4);
        acc.x += w * v.x; acc.y += w * v.y;
        acc.z += w * v.z; acc.w += w * v.w;
        ws += w;
    }
    #pragma unroll
    for (int o = 16; o; o >>= 1) {
        acc.x += __shfl_xor_sync(0xffffffffu, acc.x, o);
        acc.y += __shfl_xor_sync(0xffffffffu, acc.y, o);
        acc.z += __shfl_xor_sync(0xffffffffu, acc.z, o);
        acc.w += __shfl_xor_sync(0xffffffffu, acc.w, o);
        ws    += __shfl_xor_sync(0xffffffffu, ws, o);
    }
    float nd = g_norm_dst[gw];
    float4 o4;
    int k = lane * 4;
    o4.x = nd * (acc.x * We[k+0] + acc.y * We[128+k+0] + acc.z * We[256+k+0] + acc.w * We[384+k+0] + ws * be[k+0]);
    o4.y = nd * (acc.x * We[k+1] + acc.y * We[128+k+1] + acc.z * We[256+k+1] + acc.w * We[384+k+1] + ws * be[k+1]);
    o4.z = nd * (acc.x * We[k+2] + acc.y * We[128+k+2] + acc.z * We[256+k+2] + acc.w * We[384+k+2] + ws * be[k+2]);
    o4.w = nd * (acc.x * We[k+3] + acc.y * We[128+k+3] + acc.z * We[256+k+3] + acc.w * We[384+k+3] + ws * be[k+3]);
    *(uint2*)(out + (size_t)gw * EMB + k) = pack_half4(o4);
}

// CSR aggregation over fp16 h: warp per dst node, lane owns 4 cols. fp16 out.
__global__ void k_spmm16(const __half* __restrict__ h, __half* __restrict__ out) {
    int gw = (blockIdx.x * blockDim.x + threadIdx.x) >> 5;
    int lane = threadIdx.x & 31;
    if (gw >= NN) return;
    int beg = g_row_ptr[gw];
    int end = g_row_ptr[gw + 1];
    float4 acc = make_float4(0.f, 0.f, 0.f, 0.f);
    int j = beg;
    for (; j + 4 <= end; j += 4) {
        int2 e0 = __ldg(&g_edge[j]);
        int2 e1 = __ldg(&g_edge[j + 1]);
        int2 e2 = __ldg(&g_edge[j + 2]);
        int2 e3 = __ldg(&g_edge[j + 3]);
        uint2 r0 = __ldg((const uint2*)(h + (size_t)e0.x * EMB + lane * 4));
        uint2 r1 = __ldg((const uint2*)(h + (size_t)e1.x * EMB + lane * 4));
        uint2 r2 = __ldg((const uint2*)(h + (size_t)e2.x * EMB + lane * 4));
        uint2 r3 = __ldg((const uint2*)(h + (size_t)e3.x * EMB + lane * 4));
        float w0 = __int_as_float(e0.y);
        float w1 = __int_as_float(e1.y);
        float w2 = __int_as_float(e2.y);
        float w3 = __int_as_float(e3.y);
        float2 a0 = __half22float2(*(const __half2*)&r0.x);
        float2 b0 = __half22float2(*(const __half2*)&r0.y);
        float2 a1 = __half22float2(*(const __half2*)&r1.x);
        float2 b1 = __half22float2(*(const __half2*)&r1.y);
        float2 a2 = __half22float2(*(const __half2*)&r2.x);
        float2 b2 = __half22float2(*(const __half2*)&r2.y);
        float2 a3 = __half22float2(*(const __half2*)&r3.x);
        float2 b3 = __half22float2(*(const __half2*)&r3.y);
        acc.x += w0 * a0.x + w1 * a1.x + w2 * a2.x + w3 * a3.x;
        acc.y += w0 * a0.y + w1 * a1.y + w2 * a2.y + w3 * a3.y;
        acc.z += w0 * b0.x + w1 * b1.x + w2 * b2.x + w3 * b3.x;
        acc.w += w0 * b0.y + w1 * b1.y + w2 * b2.y + w3 * b3.y;
    }
    for (; j < end; j++) {
        int2 e0 = __ldg(&g_edge[j]);
        float w0 = __int_as_float(e0.y);
        uint2 r0 = __ldg((const uint2*)(h + (size_t)e0.x * EMB + lane * 4));
        float2 a0 = __half22float2(*(const __half2*)&r0.x);
        float2 b0 = __half22float2(*(const __half2*)&r0.y);
        acc.x += w0 * a0.x;
        acc.y += w0 * a0.y;
        acc.z += w0 * b0.x;
        acc.w += w0 * b0.y;
    }
    float nd = g_norm_dst[gw];
    acc.x *= nd; acc.y *= nd; acc.z *= nd; acc.w *= nd;
    *(uint2*)(out + (size_t)gw * EMB + lane * 4) = pack_half4(acc);
}

// ---------------------------------------------------------------
__device__ __forceinline__ uint32_t f2tf32(float f) {
    uint32_t r;
    asm("cvt.rna.tf32.f32 %0, %1;" : "=r"(r) : "f"(f));
    return r;
}

// stage a 128x32 fp16 A-chunk into As[k][m] (tf32 bits; fp16->fp32 is exact)
__device__ __forceinline__ void stage_A16(uint32_t* As, const __half* __restrict__ A,
                                          int row0, int k0, int M, int tid) {
    #pragma unroll
    for (int it = 0; it < 4; it++) {
        int f  = tid + it * 256;
        int m  = f >> 3;
        int kq = (f & 7) << 2;
        int gr = row0 + m;
        uint2 raw = make_uint2(0u, 0u);
        if (gr < M) raw = *(const uint2*)(A + (size_t)gr * 128 + k0 + kq);
        float2 a01 = __half22float2(*(const __half2*)&raw.x);
        float2 a23 = __half22float2(*(const __half2*)&raw.y);
        As[(kq + 0) * 132 + m] = __float_as_uint(a01.x);
        As[(kq + 1) * 132 + m] = __float_as_uint(a01.y);
        As[(kq + 2) * 132 + m] = __float_as_uint(a23.x);
        As[(kq + 3) * 132 + m] = __float_as_uint(a23.y);
    }
}

// stage a 32x128 fp32 W-chunk into Ws[k][n] as tf32
__device__ __forceinline__ void stage_W(uint32_t* Ws, const float* __restrict__ W,
                                        int k0, int tid) {
    #pragma unroll
    for (int it = 0; it < 4; it++) {
        int f = tid + it * 256;
        int k = f >> 5;
        int n = (f & 31) << 2;
        float4 w = *(const float4*)(W + (size_t)(k0 + k) * 128 + n);
        Ws[k * 132 + n + 0] = f2tf32(w.x);
        Ws[k * 132 + n + 1] = f2tf32(w.y);
        Ws[k * 132 + n + 2] = f2tf32(w.z);
        Ws[k * 132 + n + 3] = f2tf32(w.w);
    }
}

// one BK=32 mma sweep: c += As-chunk @ Ws-chunk
__device__ __forceinline__ void mma_sweep(const uint32_t* As, const uint32_t* Ws,
                                          float c[2][8][4],
                                          int wm, int wn, int lg, int lt) {
    #pragma unroll
    for (int ks = 0; ks < 32; ks += 8) {
        uint32_t af[2][4];
        #pragma unroll
        for (int mt = 0; mt < 2; mt++) {
            int m = wm * 32 + mt * 16 + lg;
            af[mt][0] = As[(ks + lt) * 132 + m];
            af[mt][1] = As[(ks + lt) * 132 + m + 8];
            af[mt][2] = As[(ks + 4 + lt) * 132 + m];
            af[mt][3] = As[(ks + 4 + lt) * 132 + m + 8];
        }
        #pragma unroll
        for (int nt = 0; nt < 8; nt++) {
            int n = wn * 64 + nt * 8 + lg;
            uint32_t b0 = Ws[(ks + lt) * 132 + n];
            uint32_t b1 = Ws[(ks + 4 + lt) * 132 + n];
            #pragma unroll
            for (int mt = 0; mt < 2; mt++) {
                asm volatile(
                    "mma.sync.aligned.m16n8k8.row.col.f32.tf32.tf32.f32 "
                    "{%0,%1,%2,%3}, {%4,%5,%6,%7}, {%8,%9}, {%0,%1,%2,%3};"
                    : "+f"(c[mt][nt][0]), "+f"(c[mt][nt][1]),
                      "+f"(c[mt][nt][2]), "+f"(c[mt][nt][3])
                    : "r"(af[mt][0]), "r"(af[mt][1]),
                      "r"(af[mt][2]), "r"(af[mt][3]),
                      "r"(b0), "r"(b1));
            }
        }
    }
}

// Tensor-core GEMM: C16 = relu(A16 @ W + bias), fp16 in/out, tf32 mma.
__global__ void __launch_bounds__(256)
k_gemm_tc16(const __half* __restrict__ A, const float* __restrict__ W,
            const float* __restrict__ bias, __half* __restrict__ C, int M) {
    __shared__ uint32_t As[32 * 132];
    __shared__ uint32_t Ws[32 * 132];
    int tid  = threadIdx.x;
    int warp = tid >> 5, lane = tid & 31;
    int wm = warp & 3, wn = warp >> 2;
    int lg = lane >> 2, lt = lane & 3;
    int row0 = blockIdx.x * 128;

    float c[2][8][4] = {};

    for (int k0 = 0; k0 < 128; k0 += 32) {
        stage_A16(As, A, row0, k0, M, tid);
        stage_W(Ws, W, k0, tid);
        __syncthreads();
        mma_sweep(As, Ws, c, wm, wn, lg, lt);
        __syncthreads();
    }

    #pragma unroll
    for (int nt = 0; nt < 8; nt++) {
        int col = wn * 64 + nt * 8 + 2 * lt;
        float2 bv = *(const float2*)(bias + col);
        #pragma unroll
        for (int mt = 0; mt < 2; mt++) {
            int r = row0 + wm * 32 + mt * 16 + lg;
            float2 o0, o1;
            o0.x = fmaxf(c[mt][nt][0] + bv.x, 0.f);
            o0.y = fmaxf(c[mt][nt][1] + bv.y, 0.f);
            o1.x = fmaxf(c[mt][nt][2] + bv.x, 0.f);
            o1.y = fmaxf(c[mt][nt][3] + bv.y, 0.f);
            if (r < M)     *(__half2*)(C + (size_t)r * 128 + col)       = __float22half2_rn(o0);
            if (r + 8 < M) *(__half2*)(C + (size_t)(r + 8) * 128 + col) = __float22half2_rn(o1);
        }
    }
}

// ---------------------------------------------------------------
// Fused layer3 + head: h = relu(A16 @ W3 + b3) (kept in smem as tf32),
// then out[r] = relu(h @ Wo1 + bo1) . w2 + b2.
// dyn smem: Hs[128*132] | Ws2[32*132]  (phase-1 As/Ws alias the Hs region)
__global__ void __launch_bounds__(256)
k_gemm3_head(const __half* __restrict__ A, const float* __restrict__ W3,
             const float* __restrict__ b3, const float* __restrict__ Wo1,
             const float* __restrict__ bo1, const float* __restrict__ w2,
             const float* __restrict__ b2, float* __restrict__ out, int M) {
    extern __shared__ uint32_t sm[];
    uint32_t* Hs  = sm;                 // [128][132] tf32 h tile (phase 2 A)
    uint32_t* As1 = sm;                 // phase-1 staging aliases Hs
    uint32_t* Ws1 = sm + 32 * 132;
    uint32_t* Ws2 = sm + 128 * 132;     // phase-2 W staging
    __shared__ float red[128];
    __shared__ float w2s[128];

    int tid  = threadIdx.x;
    int warp = tid >> 5, lane = tid & 31;
    int wm = warp & 3, wn = warp >> 2;
    int lg = lane >> 2, lt = lane & 3;
    int row0 = blockIdx.x * 128;

    if (tid < 128) { red[tid] = 0.f; w2s[tid] = w2[tid]; }

    // ---- phase 1: c = A @ W3 ----
    float c[2][8][4] = {};
    for (int k0 = 0; k0 < 128; k0 += 32) {
        stage_A16(As1, A, row0, k0, M, tid);
        stage_W(Ws1, W3, k0, tid);
        __syncthreads();
        mma_sweep(As1, Ws1, c, wm, wn, lg, lt);
        __syncthreads();
    }

    // ---- phase 1.5: h = relu(c + b3) -> Hs[k=col][m=row] (tf32) ----
    #pragma unroll
    for (int nt = 0; nt < 8; nt++) {
        int col = wn * 64 + nt * 8 + 2 * lt;
        float2 bv = *(const float2*)(b3 + col);
        #pragma unroll
        for (int mt = 0; mt < 2; mt++) {
            int r = wm * 32 + mt * 16 + lg;
            Hs[(col + 0) * 132 + r]     = f2tf32(fmaxf(c[mt][nt][0] + bv.x, 0.f));
            Hs[(col + 1) * 132 + r]     = f2tf32(fmaxf(c[mt][nt][1] + bv.y, 0.f));
            Hs[(col + 0) * 132 + r + 8] = f2tf32(fmaxf(c[mt][nt][2] + bv.x, 0.f));
            Hs[(col + 1) * 132 + r + 8] = f2tf32(fmaxf(c[mt][nt][3] + bv.y, 0.f));
        }
    }

    // ---- phase 2: c2 = h @ Wo1 ----
    float c2[2][8][4] = {};
    for (int kc = 0; kc < 4; kc++) {
        int k0 = kc * 32;
        stage_W(Ws2, Wo1, k0, tid);
        __syncthreads();   // also orders Hs writes before first read
        mma_sweep(Hs + k0 * 132, Ws2, c2, wm, wn, lg, lt);
        __syncthreads();
    }

    // ---- head epilogue: relu(c2 + bo1) . w2 -> reduce -> out ----
    #pragma unroll
    for (int mt = 0; mt < 2; mt++) {
        float dot0 = 0.f, dot1 = 0.f;
        #pragma unroll
        for (int nt = 0; nt < 8; nt++) {
            int col = wn * 64 + nt * 8 + 2 * lt;
            float2 bv = *(const float2*)(bo1 + col);
            float wa = w2s[col], wb = w2s[col + 1];
            dot0 += fmaxf(c2[mt][nt][0] + bv.x, 0.f) * wa
                  + fmaxf(c2[mt][nt][1] + bv.y, 0.f) * wb;
            dot1 += fmaxf(c2[mt][nt][2] + bv.x, 0.f) * wa
                  + fmaxf(c2[mt][nt][3] + bv.y, 0.f) * wb;
        }
        int rl = wm * 32 + mt * 16 + lg;
        atomicAdd(&red[rl], dot0);
        atomicAdd(&red[rl + 8], dot1);
    }
    __syncthreads();
    if (tid < 128 && row0 + tid < M)
        out[row0 + tid] = red[tid] + b2[0];
}

// ---------------------------------------------------------------
extern "C" void kernel_launch(void* const* d_in, const int* in_sizes, int n_in,
                              void* d_out, int out_size) {
    const float* nf   = (const float*)d_in[0];
    const int*   src  = (const int*)d_in[1];
    const int*   dst  = (const int*)d_in[2];
    const float* Wemb = (const float*)d_in[3];
    const float* bemb = (const float*)d_in[4];
    const float* Wg   = (const float*)d_in[5];
    const float* bg   = (const float*)d_in[6];
    const float* Wo1  = (const float*)d_in[7];
    const float* bo1  = (const float*)d_in[8];
    const float* Wo2  = (const float*)d_in[9];
    const float* bo2  = (const float*)d_in[10];
    float* out = (float*)d_out;

    __half *agg, *h16;
    cudaGetSymbolAddress((void**)&agg, g_agg);
    cudaGetSymbolAddress((void**)&h16, g_h16);

    const int SM_HEAD = (128 * 132 + 32 * 132) * 4;   // 84480 bytes
    cudaFuncSetAttribute(k_gemm3_head,
                         cudaFuncAttributeMaxDynamicSharedMemorySize, SM_HEAD);

    const int NB_EDGE = (NE + 255) / 256;
    const int NB_WARP = (NN * 32 + 255) / 256;   // warp-per-node kernels

    k_count<<<NB_EDGE, 256>>>(src, dst);                        // 0
    k_scanA<<<SCAN_BLOCKS, 256>>>();                            // 1
    k_scanB<<<SCAN_BLOCKS, 256>>>();                            // 2
    k_fill<<<NB_EDGE, 256>>>(src, dst);                         // 3

    // layer 1: fused embed+aggregate -> agg, then GEMM -> h16
    k_spmm_l1<<<NB_WARP, 256>>>(nf, Wemb, bemb, agg);           // 4
    k_gemm_tc16<<<NB_TILE, 256>>>(agg, Wg, bg, h16, NN);        // 5

    // layer 2
    k_spmm16<<<NB_WARP, 256>>>(h16, agg);                       // 6
    k_gemm_tc16<<<NB_TILE, 256>>>(agg, Wg + 128 * 128,
                                  bg + 128, h16, NN);           // 7
    // layer 3 aggregate
    k_spmm16<<<NB_WARP, 256>>>(h16, agg);                       // 8

    // fused layer-3 GEMM + head -> out
    k_gemm3_head<<<NB_TILE, 256, SM_HEAD>>>(agg, Wg + 2 * 128 * 128,
                                            bg + 2 * 128, Wo1, bo1,
                                            Wo2, bo2, out, NN);  // 9
}

// round 11
// speedup vs baseline: 1.5788x; 1.3759x over previous
#include <cuda_runtime.h>
#include <cuda_fp16.h>
#include <cstdint>

#define NN 50000
#define NE 640000
#define EMB 128
#define SCAN_BLOCKS 196   // 196*256 = 50176 >= NN
#define NB_TILE 391       // (NN+127)/128
#define SW 68             // smem row stride in uint32 words (64 data + 4 pad)

// ---- scratch (device globals; zero-initialized at load, re-zeroed each launch) ----
__device__ __half g_agg[NN * EMB];    // fp16 spmm output / gemm input (12.8 MB)
__device__ __half g_h16[NN * EMB];    // fp16 gemm output / spmm gather input (12.8 MB)
__device__ float g_norm_src[NN];
__device__ float g_norm_dst[NN];
__device__ int   g_deg_src[NN];       // zeroed at end of scanB each launch
__device__ int   g_deg_dst[NN];
__device__ int   g_row_ptr[NN + 1];
__device__ int   g_cursor[NN];
__device__ int2  g_edge[NE];          // (src, __float_as_int(w)) packed
__device__ int   g_part[SCAN_BLOCKS];

// ---------------------------------------------------------------
__global__ void k_count(const int* __restrict__ src, const int* __restrict__ dst) {
    int e = blockIdx.x * blockDim.x + threadIdx.x;
    if (e < NE) {
        atomicAdd(&g_deg_src[__ldg(&src[e])], 1);
        atomicAdd(&g_deg_dst[__ldg(&dst[e])], 1);
    }
}

__global__ void k_scanA() {
    __shared__ int sh[256];
    int i = blockIdx.x * 256 + threadIdx.x;
    int d = (i < NN) ? g_deg_dst[i] : 0;
    sh[threadIdx.x] = d;
    __syncthreads();
    #pragma unroll
    for (int off = 128; off; off >>= 1) {
        if (threadIdx.x < off) sh[threadIdx.x] += sh[threadIdx.x + off];
        __syncthreads();
    }
    if (threadIdx.x == 0) g_part[blockIdx.x] = sh[0];
}

__global__ void k_scanB() {
    __shared__ int sh[256];
    __shared__ int pre;
    int tid = threadIdx.x;
    int b = blockIdx.x;
    int pv = (tid < b) ? g_part[tid] : 0;
    sh[tid] = pv;
    __syncthreads();
    #pragma unroll
    for (int off = 128; off; off >>= 1) {
        if (tid < off) sh[tid] += sh[tid + off];
        __syncthreads();
    }
    if (tid == 0) pre = sh[0];
    __syncthreads();
    int prefix = pre;
    __syncthreads();

    int i = b * 256 + tid;
    int d = (i < NN) ? g_deg_dst[i] : 0;
    sh[tid] = d;
    __syncthreads();
    #pragma unroll
    for (int off = 1; off < 256; off <<= 1) {
        int v = (tid >= off) ? sh[tid - off] : 0;
        __syncthreads();
        sh[tid] += v;
        __syncthreads();
    }
    int incl = sh[tid];
    int excl = incl - d;
    if (i < NN) {
        int base = prefix + excl;
        g_row_ptr[i] = base;
        g_cursor[i]  = base;
        if (i == NN - 1) g_row_ptr[NN] = prefix + incl;
        int ds = g_deg_src[i];
        g_norm_dst[i] = rsqrtf((float)max(d, 1));
        g_norm_src[i] = rsqrtf((float)max(ds, 1));
        g_deg_dst[i] = 0;
        g_deg_src[i] = 0;
    }
}

__global__ void k_fill(const int* __restrict__ src, const int* __restrict__ dst) {
    int e = blockIdx.x * blockDim.x + threadIdx.x;
    if (e < NE) {
        int s = __ldg(&src[e]);
        int pos = atomicAdd(&g_cursor[__ldg(&dst[e])], 1);
        g_edge[pos] = make_int2(s, __float_as_int(g_norm_src[s]));
    }
}

// ---------------------------------------------------------------
__device__ __forceinline__ uint2 pack_half4(float4 v) {
    __half2 lo = __float22half2_rn(make_float2(v.x, v.y));
    __half2 hi = __float22half2_rn(make_float2(v.z, v.w));
    uint2 r;
    r.x = *(uint32_t*)&lo;
    r.y = *(uint32_t*)&hi;
    return r;
}

// Layer-1 fused aggregate: warp per dst node. writes fp16 agg.
__global__ void __launch_bounds__(256)
k_spmm_l1(const float* __restrict__ nf, const float* __restrict__ Wemb,
          const float* __restrict__ bemb, __half* __restrict__ out) {
    __shared__ float We[512];
    __shared__ float be[128];
    int tid = threadIdx.x;
    if (tid < 256) {
        We[tid] = Wemb[tid];
        We[tid + 256] = Wemb[tid + 256];
        if (tid < 128) be[tid] = bemb[tid];
    }
    __syncthreads();

    int gw = (blockIdx.x * blockDim.x + tid) >> 5;
    int lane = tid & 31;
    if (gw >= NN) return;
    int beg = g_row_ptr[gw];
    int end = g_row_ptr[gw + 1];
    float4 acc = make_float4(0.f, 0.f, 0.f, 0.f);
    float ws = 0.f;
    for (int j = beg + lane; j < end; j += 32) {
        int2 e = __ldg(&g_edge[j]);
        float w = __int_as_float(e.y);
        float4 v = *(const float4*)(nf + (size_t)e.x * 4);
        acc.x += w * v.x; acc.y += w * v.y;
        acc.z += w * v.z; acc.w += w * v.w;
        ws += w;
    }
    #pragma unroll
    for (int o = 16; o; o >>= 1) {
        acc.x += __shfl_xor_sync(0xffffffffu, acc.x, o);
        acc.y += __shfl_xor_sync(0xffffffffu, acc.y, o);
        acc.z += __shfl_xor_sync(0xffffffffu, acc.z, o);
        acc.w += __shfl_xor_sync(0xffffffffu, acc.w, o);
        ws    += __shfl_xor_sync(0xffffffffu, ws, o);
    }
    float nd = g_norm_dst[gw];
    float4 o4;
    int k = lane * 4;
    o4.x = nd * (acc.x * We[k+0] + acc.y * We[128+k+0] + acc.z * We[256+k+0] + acc.w * We[384+k+0] + ws * be[k+0]);
    o4.y = nd * (acc.x * We[k+1] + acc.y * We[128+k+1] + acc.z * We[256+k+1] + acc.w * We[384+k+1] + ws * be[k+1]);
    o4.z = nd * (acc.x * We[k+2] + acc.y * We[128+k+2] + acc.z * We[256+k+2] + acc.w * We[384+k+2] + ws * be[k+2]);
    o4.w = nd * (acc.x * We[k+3] + acc.y * We[128+k+3] + acc.z * We[256+k+3] + acc.w * We[384+k+3] + ws * be[k+3]);
    *(uint2*)(out + (size_t)gw * EMB + k) = pack_half4(o4);
}

// CSR aggregation over fp16 h: warp per dst node, lane owns 4 cols. fp16 out.
__global__ void k_spmm16(const __half* __restrict__ h, __half* __restrict__ out) {
    int gw = (blockIdx.x * blockDim.x + threadIdx.x) >> 5;
    int lane = threadIdx.x & 31;
    if (gw >= NN) return;
    int beg = g_row_ptr[gw];
    int end = g_row_ptr[gw + 1];
    float4 acc = make_float4(0.f, 0.f, 0.f, 0.f);
    int j = beg;
    for (; j + 4 <= end; j += 4) {
        int2 e0 = __ldg(&g_edge[j]);
        int2 e1 = __ldg(&g_edge[j + 1]);
        int2 e2 = __ldg(&g_edge[j + 2]);
        int2 e3 = __ldg(&g_edge[j + 3]);
        uint2 r0 = __ldg((const uint2*)(h + (size_t)e0.x * EMB + lane * 4));
        uint2 r1 = __ldg((const uint2*)(h + (size_t)e1.x * EMB + lane * 4));
        uint2 r2 = __ldg((const uint2*)(h + (size_t)e2.x * EMB + lane * 4));
        uint2 r3 = __ldg((const uint2*)(h + (size_t)e3.x * EMB + lane * 4));
        float w0 = __int_as_float(e0.y);
        float w1 = __int_as_float(e1.y);
        float w2 = __int_as_float(e2.y);
        float w3 = __int_as_float(e3.y);
        float2 a0 = __half22float2(*(const __half2*)&r0.x);
        float2 b0 = __half22float2(*(const __half2*)&r0.y);
        float2 a1 = __half22float2(*(const __half2*)&r1.x);
        float2 b1 = __half22float2(*(const __half2*)&r1.y);
        float2 a2 = __half22float2(*(const __half2*)&r2.x);
        float2 b2 = __half22float2(*(const __half2*)&r2.y);
        float2 a3 = __half22float2(*(const __half2*)&r3.x);
        float2 b3 = __half22float2(*(const __half2*)&r3.y);
        acc.x += w0 * a0.x + w1 * a1.x + w2 * a2.x + w3 * a3.x;
        acc.y += w0 * a0.y + w1 * a1.y + w2 * a2.y + w3 * a3.y;
        acc.z += w0 * b0.x + w1 * b1.x + w2 * b2.x + w3 * b3.x;
        acc.w += w0 * b0.y + w1 * b1.y + w2 * b2.y + w3 * b3.y;
    }
    for (; j < end; j++) {
        int2 e0 = __ldg(&g_edge[j]);
        float w0 = __int_as_float(e0.y);
        uint2 r0 = __ldg((const uint2*)(h + (size_t)e0.x * EMB + lane * 4));
        float2 a0 = __half22float2(*(const __half2*)&r0.x);
        float2 b0 = __half22float2(*(const __half2*)&r0.y);
        acc.x += w0 * a0.x;
        acc.y += w0 * a0.y;
        acc.z += w0 * b0.x;
        acc.w += w0 * b0.y;
    }
    float nd = g_norm_dst[gw];
    acc.x *= nd; acc.y *= nd; acc.z *= nd; acc.w *= nd;
    *(uint2*)(out + (size_t)gw * EMB + lane * 4) = pack_half4(acc);
}

// ---------------------------------------------------------------
// fp16 tensor-core GEMM machinery (m16n8k16, fp32 accumulate).
// Ah: fp16 A tile [m][k] packed half2 along k, stride SW words.
// Wh: fp16 W^T tile [n][k] packed half2 along k, stride SW words.

// stage full 128x128 fp16 A tile (raw copy; rows >= M zeroed)
__device__ __forceinline__ void stage_Ah(uint32_t* Ah, const __half* __restrict__ A,
                                         int row0, int M, int tid) {
    #pragma unroll
    for (int it = 0; it < 16; it++) {
        int f = tid + it * 256;      // 0..4095
        int m = f >> 5;              // 0..127
        int u = f & 31;              // uint2 index within row
        int gr = row0 + m;
        uint2 raw = make_uint2(0u, 0u);
        if (gr < M) raw = *(const uint2*)(A + (size_t)gr * 128 + u * 4);
        Ah[m * SW + u * 2]     = raw.x;
        Ah[m * SW + u * 2 + 1] = raw.y;
    }
}

// stage full 128x128 fp32 W, transposed, as fp16 [n][k].
// 256 threads, 2 per row (p=0 covers words 0..31, p=1 covers 32..63).
__device__ __forceinline__ void stage_WhT(uint32_t* Wh, const float* __restrict__ W,
                                          int tid) {
    int n = tid & 127;
    int p = tid >> 7;
    #pragma unroll
    for (int w = 0; w < 32; w++) {
        int word = p * 32 + w;        // 0..63
        int k = word * 2;
        float lo = __ldg(&W[(size_t)k * 128 + n]);
        float hi = __ldg(&W[(size_t)(k + 1) * 128 + n]);
        __half2 hh = __float22half2_rn(make_float2(lo, hi));
        Wh[n * SW + word] = *(uint32_t*)&hh;
    }
}

// full-K (128) mma sweep: c += Ah @ Wh^T
__device__ __forceinline__ void mma_fullk(const uint32_t* Ah, const uint32_t* Wh,
                                          float c[2][8][4],
                                          int wm, int wn, int lg, int lt) {
    #pragma unroll
    for (int kw = 0; kw < 64; kw += 8) {   // 16 K-elements per step
        uint32_t af[2][4];
        #pragma unroll
        for (int mt = 0; mt < 2; mt++) {
            int m = wm * 32 + mt * 16 + lg;
            const uint32_t* r0 = Ah + m * SW + kw;
            const uint32_t* r1 = Ah + (m + 8) * SW + kw;
            af[mt][0] = r0[lt];
            af[mt][1] = r1[lt];
            af[mt][2] = r0[lt + 4];
            af[mt][3] = r1[lt + 4];
        }
        #pragma unroll
        for (int nt = 0; nt < 8; nt++) {
            int n = wn * 64 + nt * 8 + lg;
            uint32_t b0 = Wh[n * SW + kw + lt];
            uint32_t b1 = Wh[n * SW + kw + 4 + lt];
            #pragma unroll
            for (int mt = 0; mt < 2; mt++) {
                asm volatile(
                    "mma.sync.aligned.m16n8k16.row.col.f32.f16.f16.f32 "
                    "{%0,%1,%2,%3}, {%4,%5,%6,%7}, {%8,%9}, {%0,%1,%2,%3};"
                    : "+f"(c[mt][nt][0]), "+f"(c[mt][nt][1]),
                      "+f"(c[mt][nt][2]), "+f"(c[mt][nt][3])
                    : "r"(af[mt][0]), "r"(af[mt][1]),
                      "r"(af[mt][2]), "r"(af[mt][3]),
                      "r"(b0), "r"(b1));
            }
        }
    }
}

// GEMM: C16 = relu(A16 @ W + bias).  dyn smem: Ah | Wh (2 x 128*SW words)
__global__ void __launch_bounds__(256)
k_gemm_tc16(const __half* __restrict__ A, const float* __restrict__ W,
            const float* __restrict__ bias, __half* __restrict__ C, int M) {
    extern __shared__ uint32_t sm[];
    uint32_t* Ah = sm;
    uint32_t* Wh = sm + 128 * SW;
    int tid  = threadIdx.x;
    int warp = tid >> 5, lane = tid & 31;
    int wm = warp & 3, wn = warp >> 2;
    int lg = lane >> 2, lt = lane & 3;
    int row0 = blockIdx.x * 128;

    stage_Ah(Ah, A, row0, M, tid);
    stage_WhT(Wh, W, tid);
    __syncthreads();

    float c[2][8][4] = {};
    mma_fullk(Ah, Wh, c, wm, wn, lg, lt);

    #pragma unroll
    for (int nt = 0; nt < 8; nt++) {
        int col = wn * 64 + nt * 8 + 2 * lt;
        float2 bv = *(const float2*)(bias + col);
        #pragma unroll
        for (int mt = 0; mt < 2; mt++) {
            int r = row0 + wm * 32 + mt * 16 + lg;
            float2 o0, o1;
            o0.x = fmaxf(c[mt][nt][0] + bv.x, 0.f);
            o0.y = fmaxf(c[mt][nt][1] + bv.y, 0.f);
            o1.x = fmaxf(c[mt][nt][2] + bv.x, 0.f);
            o1.y = fmaxf(c[mt][nt][3] + bv.y, 0.f);
            if (r < M)     *(__half2*)(C + (size_t)r * 128 + col)       = __float22half2_rn(o0);
            if (r + 8 < M) *(__half2*)(C + (size_t)(r + 8) * 128 + col) = __float22half2_rn(o1);
        }
    }
}

// ---------------------------------------------------------------
// Fused layer3 + head: h = relu(A16 @ W3 + b3) kept in smem (fp16),
// then out[r] = relu(h @ Wo1 + bo1) . w2 + b2.
__global__ void __launch_bounds__(256)
k_gemm3_head(const __half* __restrict__ A, const float* __restrict__ W3,
             const float* __restrict__ b3, const float* __restrict__ Wo1,
             const float* __restrict__ bo1, const float* __restrict__ w2,
             const float* __restrict__ b2, float* __restrict__ out, int M) {
    extern __shared__ uint32_t sm[];
    uint32_t* Ah = sm;               // phase-1 A tile; reused as h tile
    uint32_t* Wh = sm + 128 * SW;    // phase-1 W3^T; reused for Wo1^T
    __shared__ float red[128];
    __shared__ float w2s[128];

    int tid  = threadIdx.x;
    int warp = tid >> 5, lane = tid & 31;
    int wm = warp & 3, wn = warp >> 2;
    int lg = lane >> 2, lt = lane & 3;
    int row0 = blockIdx.x * 128;

    if (tid < 128) { red[tid] = 0.f; w2s[tid] = w2[tid]; }

    // phase 1: c = A @ W3
    stage_Ah(Ah, A, row0, M, tid);
    stage_WhT(Wh, W3, tid);
    __syncthreads();
    float c[2][8][4] = {};
    mma_fullk(Ah, Wh, c, wm, wn, lg, lt);
    __syncthreads();   // all warps done reading Ah/Wh

    // phase 1.5: h = relu(c + b3) -> Ah as fp16 [m][k]; stage Wo1^T -> Wh
    #pragma unroll
    for (int nt = 0; nt < 8; nt++) {
        int col = wn * 64 + nt * 8 + 2 * lt;
        float2 bv = *(const float2*)(b3 + col);
        int widx = col >> 1;
        #pragma unroll
        for (int mt = 0; mt < 2; mt++) {
            int r = wm * 32 + mt * 16 + lg;
            __half2 h0 = __float22half2_rn(make_float2(
                fmaxf(c[mt][nt][0] + bv.x, 0.f), fmaxf(c[mt][nt][1] + bv.y, 0.f)));
            __half2 h1 = __float22half2_rn(make_float2(
                fmaxf(c[mt][nt][2] + bv.x, 0.f), fmaxf(c[mt][nt][3] + bv.y, 0.f)));
            Ah[r * SW + widx]       = *(uint32_t*)&h0;
            Ah[(r + 8) * SW + widx] = *(uint32_t*)&h1;
        }
    }
    stage_WhT(Wh, Wo1, tid);
    __syncthreads();

    // phase 2: c2 = h @ Wo1
    float c2[2][8][4] = {};
    mma_fullk(Ah, Wh, c2, wm, wn, lg, lt);

    // head epilogue: relu(c2 + bo1) . w2 -> reduce -> out
    #pragma unroll
    for (int mt = 0; mt < 2; mt++) {
        float dot0 = 0.f, dot1 = 0.f;
        #pragma unroll
        for (int nt = 0; nt < 8; nt++) {
            int col = wn * 64 + nt * 8 + 2 * lt;
            float2 bv = *(const float2*)(bo1 + col);
            float wa = w2s[col], wb = w2s[col + 1];
            dot0 += fmaxf(c2[mt][nt][0] + bv.x, 0.f) * wa
                  + fmaxf(c2[mt][nt][1] + bv.y, 0.f) * wb;
            dot1 += fmaxf(c2[mt][nt][2] + bv.x, 0.f) * wa
                  + fmaxf(c2[mt][nt][3] + bv.y, 0.f) * wb;
        }
        int rl = wm * 32 + mt * 16 + lg;
        atomicAdd(&red[rl], dot0);
        atomicAdd(&red[rl + 8], dot1);
    }
    __syncthreads();
    if (tid < 128 && row0 + tid < M)
        out[row0 + tid] = red[tid] + b2[0];
}

// ---------------------------------------------------------------
extern "C" void kernel_launch(void* const* d_in, const int* in_sizes, int n_in,
                              void* d_out, int out_size) {
    const float* nf   = (const float*)d_in[0];
    const int*   src  = (const int*)d_in[1];
    const int*   dst  = (const int*)d_in[2];
    const float* Wemb = (const float*)d_in[3];
    const float* bemb = (const float*)d_in[4];
    const float* Wg   = (const float*)d_in[5];
    const float* bg   = (const float*)d_in[6];
    const float* Wo1  = (const float*)d_in[7];
    const float* bo1  = (const float*)d_in[8];
    const float* Wo2  = (const float*)d_in[9];
    const float* bo2  = (const float*)d_in[10];
    float* out = (float*)d_out;

    __half *agg, *h16;
    cudaGetSymbolAddress((void**)&agg, g_agg);
    cudaGetSymbolAddress((void**)&h16, g_h16);

    const int SM_GEMM = 2 * 128 * SW * 4;   // 69632 bytes
    cudaFuncSetAttribute(k_gemm_tc16,
                         cudaFuncAttributeMaxDynamicSharedMemorySize, SM_GEMM);
    cudaFuncSetAttribute(k_gemm3_head,
                         cudaFuncAttributeMaxDynamicSharedMemorySize, SM_GEMM);

    const int NB_EDGE = (NE + 255) / 256;
    const int NB_WARP = (NN * 32 + 255) / 256;   // warp-per-node kernels

    k_count<<<NB_EDGE, 256>>>(src, dst);                        // 0
    k_scanA<<<SCAN_BLOCKS, 256>>>();                            // 1
    k_scanB<<<SCAN_BLOCKS, 256>>>();                            // 2
    k_fill<<<NB_EDGE, 256>>>(src, dst);                         // 3

    // layer 1: fused embed+aggregate -> agg, then GEMM -> h16
    k_spmm_l1<<<NB_WARP, 256>>>(nf, Wemb, bemb, agg);           // 4
    k_gemm_tc16<<<NB_TILE, 256, SM_GEMM>>>(agg, Wg, bg, h16, NN);        // 5

    // layer 2
    k_spmm16<<<NB_WARP, 256>>>(h16, agg);                       // 6
    k_gemm_tc16<<<NB_TILE, 256, SM_GEMM>>>(agg, Wg + 128 * 128,
                                           bg + 128, h16, NN);  // 7
    // layer 3 aggregate
    k_spmm16<<<NB_WARP, 256>>>(h16, agg);                       // 8

    // fused layer-3 GEMM + head -> out
    k_gemm3_head<<<NB_TILE, 256, SM_GEMM>>>(agg, Wg + 2 * 128 * 128,
                                            bg + 2 * 128, Wo1, bo1,
                                            Wo2, bo2, out, NN);  // 9
}

// round 12
// speedup vs baseline: 1.5822x; 1.0021x over previous
#include <cuda_runtime.h>
#include <cuda_fp16.h>
#include <cstdint>

#define NN 50000
#define NE 640000
#define EMB 128
#define SCAN_BLOCKS 196   // 196*256 = 50176 >= NN
#define NB_TILE 391       // (NN+127)/128
#define SW 68             // smem row stride in uint32 words (64 data + 4 pad)

// ---- scratch (device globals; zero-initialized at load, re-zeroed each launch) ----
__device__ __half g_agg[NN * EMB];    // fp16 spmm output / gemm input (12.8 MB)
__device__ __half g_h16[NN * EMB];    // fp16 gemm output / spmm gather input (12.8 MB)
__device__ float g_norm_src[NN];
__device__ float g_norm_dst[NN];
__device__ int   g_deg_src[NN];       // zeroed at end of scanB each launch
__device__ int   g_deg_dst[NN];
__device__ int   g_row_ptr[NN + 1];
__device__ int   g_cursor[NN];
__device__ int   g_col[NE];           // src index only (weights folded into h rows)
__device__ int   g_part[SCAN_BLOCKS];

// ---------------------------------------------------------------
// 2 edges per thread (NE is even)
__global__ void k_count(const int* __restrict__ src, const int* __restrict__ dst) {
    int e = (blockIdx.x * blockDim.x + threadIdx.x) * 2;
    if (e < NE) {
        int2 s = *(const int2*)(src + e);
        int2 d = *(const int2*)(dst + e);
        atomicAdd(&g_deg_src[s.x], 1);
        atomicAdd(&g_deg_src[s.y], 1);
        atomicAdd(&g_deg_dst[d.x], 1);
        atomicAdd(&g_deg_dst[d.y], 1);
    }
}

__global__ void k_scanA() {
    __shared__ int sh[256];
    int i = blockIdx.x * 256 + threadIdx.x;
    int d = (i < NN) ? g_deg_dst[i] : 0;
    sh[threadIdx.x] = d;
    __syncthreads();
    #pragma unroll
    for (int off = 128; off; off >>= 1) {
        if (threadIdx.x < off) sh[threadIdx.x] += sh[threadIdx.x + off];
        __syncthreads();
    }
    if (threadIdx.x == 0) g_part[blockIdx.x] = sh[0];
}

__global__ void k_scanB() {
    __shared__ int sh[256];
    __shared__ int pre;
    int tid = threadIdx.x;
    int b = blockIdx.x;
    int pv = (tid < b) ? g_part[tid] : 0;
    sh[tid] = pv;
    __syncthreads();
    #pragma unroll
    for (int off = 128; off; off >>= 1) {
        if (tid < off) sh[tid] += sh[tid + off];
        __syncthreads();
    }
    if (tid == 0) pre = sh[0];
    __syncthreads();
    int prefix = pre;
    __syncthreads();

    int i = b * 256 + tid;
    int d = (i < NN) ? g_deg_dst[i] : 0;
    sh[tid] = d;
    __syncthreads();
    #pragma unroll
    for (int off = 1; off < 256; off <<= 1) {
        int v = (tid >= off) ? sh[tid - off] : 0;
        __syncthreads();
        sh[tid] += v;
        __syncthreads();
    }
    int incl = sh[tid];
    int excl = incl - d;
    if (i < NN) {
        int base = prefix + excl;
        g_row_ptr[i] = base;
        g_cursor[i]  = base;
        if (i == NN - 1) g_row_ptr[NN] = prefix + incl;
        int ds = g_deg_src[i];
        g_norm_dst[i] = rsqrtf((float)max(d, 1));
        g_norm_src[i] = rsqrtf((float)max(ds, 1));
        g_deg_dst[i] = 0;
        g_deg_src[i] = 0;
    }
}

// 2 edges per thread; stores bare src index
__global__ void k_fill(const int* __restrict__ src, const int* __restrict__ dst) {
    int e = (blockIdx.x * blockDim.x + threadIdx.x) * 2;
    if (e < NE) {
        int2 s = *(const int2*)(src + e);
        int2 d = *(const int2*)(dst + e);
        int p0 = atomicAdd(&g_cursor[d.x], 1);
        g_col[p0] = s.x;
        int p1 = atomicAdd(&g_cursor[d.y], 1);
        g_col[p1] = s.y;
    }
}

// ---------------------------------------------------------------
__device__ __forceinline__ uint2 pack_half4(float4 v) {
    __half2 lo = __float22half2_rn(make_float2(v.x, v.y));
    __half2 hi = __float22half2_rn(make_float2(v.z, v.w));
    uint2 r;
    r.x = *(uint32_t*)&lo;
    r.y = *(uint32_t*)&hi;
    return r;
}

// Layer-1 fused aggregate: warp per dst node. writes fp16 agg.
// w = norm_src[s] gathered directly (no per-edge weight storage).
__global__ void __launch_bounds__(256)
k_spmm_l1(const float* __restrict__ nf, const float* __restrict__ Wemb,
          const float* __restrict__ bemb, __half* __restrict__ out) {
    __shared__ float We[512];
    __shared__ float be[128];
    int tid = threadIdx.x;
    if (tid < 256) {
        We[tid] = Wemb[tid];
        We[tid + 256] = Wemb[tid + 256];
        if (tid < 128) be[tid] = bemb[tid];
    }
    __syncthreads();

    int gw = (blockIdx.x * blockDim.x + tid) >> 5;
    int lane = tid & 31;
    if (gw >= NN) return;
    int beg = g_row_ptr[gw];
    int end = g_row_ptr[gw + 1];
    float4 acc = make_float4(0.f, 0.f, 0.f, 0.f);
    float ws = 0.f;
    for (int j = beg + lane; j < end; j += 32) {
        int s = __ldg(&g_col[j]);
        float w = __ldg(&g_norm_src[s]);
        float4 v = *(const float4*)(nf + (size_t)s * 4);
        acc.x += w * v.x; acc.y += w * v.y;
        acc.z += w * v.z; acc.w += w * v.w;
        ws += w;
    }
    #pragma unroll
    for (int o = 16; o; o >>= 1) {
        acc.x += __shfl_xor_sync(0xffffffffu, acc.x, o);
        acc.y += __shfl_xor_sync(0xffffffffu, acc.y, o);
        acc.z += __shfl_xor_sync(0xffffffffu, acc.z, o);
        acc.w += __shfl_xor_sync(0xffffffffu, acc.w, o);
        ws    += __shfl_xor_sync(0xffffffffu, ws, o);
    }
    float nd = g_norm_dst[gw];
    float4 o4;
    int k = lane * 4;
    o4.x = nd * (acc.x * We[k+0] + acc.y * We[128+k+0] + acc.z * We[256+k+0] + acc.w * We[384+k+0] + ws * be[k+0]);
    o4.y = nd * (acc.x * We[k+1] + acc.y * We[128+k+1] + acc.z * We[256+k+1] + acc.w * We[384+k+1] + ws * be[k+1]);
    o4.z = nd * (acc.x * We[k+2] + acc.y * We[128+k+2] + acc.z * We[256+k+2] + acc.w * We[384+k+2] + ws * be[k+2]);
    o4.w = nd * (acc.x * We[k+3] + acc.y * We[128+k+3] + acc.z * We[256+k+3] + acc.w * We[384+k+3] + ws * be[k+3]);
    *(uint2*)(out + (size_t)gw * EMB + k) = pack_half4(o4);
}

// ---------------------------------------------------------------
__device__ __forceinline__ void acc8(float* a, uint4 r) {
    float2 t;
    t = __half22float2(*(const __half2*)&r.x); a[0] += t.x; a[1] += t.y;
    t = __half22float2(*(const __half2*)&r.y); a[2] += t.x; a[3] += t.y;
    t = __half22float2(*(const __half2*)&r.z); a[4] += t.x; a[5] += t.y;
    t = __half22float2(*(const __half2*)&r.w); a[6] += t.x; a[7] += t.y;
}

// Weightless CSR aggregation: warp per dst node; half-warp owns an edge
// stream, lane owns 8 columns (uint4 = 16B). h rows are pre-scaled by
// norm_src in the GEMM epilogue.
__global__ void k_spmm16(const __half* __restrict__ h, __half* __restrict__ out) {
    int gw = (blockIdx.x * blockDim.x + threadIdx.x) >> 5;
    int lane = threadIdx.x & 31;
    if (gw >= NN) return;
    int beg = g_row_ptr[gw];
    int end = g_row_ptr[gw + 1];
    int half = lane >> 4;     // edge-stream id
    int l = lane & 15;        // column group: halves [l*8, l*8+8)
    const __half* hb = h + l * 8;

    float acc[8] = {};
    int j = beg + half;
    for (; j + 2 < end; j += 4) {
        int s0 = __ldg(&g_col[j]);
        int s1 = __ldg(&g_col[j + 2]);
        uint4 r0 = __ldg((const uint4*)(hb + (size_t)s0 * EMB));
        uint4 r1 = __ldg((const uint4*)(hb + (size_t)s1 * EMB));
        acc8(acc, r0);
        acc8(acc, r1);
    }
    if (j < end) {
        int s0 = __ldg(&g_col[j]);
        uint4 r0 = __ldg((const uint4*)(hb + (size_t)s0 * EMB));
        acc8(acc, r0);
    }
    // combine the two edge streams
    #pragma unroll
    for (int i = 0; i < 8; i++)
        acc[i] += __shfl_xor_sync(0xffffffffu, acc[i], 16);

    if (half == 0) {
        float nd = g_norm_dst[gw];
        uint4 o;
        __half2 p;
        p = __float22half2_rn(make_float2(acc[0] * nd, acc[1] * nd)); o.x = *(uint32_t*)&p;
        p = __float22half2_rn(make_float2(acc[2] * nd, acc[3] * nd)); o.y = *(uint32_t*)&p;
        p = __float22half2_rn(make_float2(acc[4] * nd, acc[5] * nd)); o.z = *(uint32_t*)&p;
        p = __float22half2_rn(make_float2(acc[6] * nd, acc[7] * nd)); o.w = *(uint32_t*)&p;
        *(uint4*)(out + (size_t)gw * EMB + l * 8) = o;
    }
}

// ---------------------------------------------------------------
// fp16 tensor-core GEMM machinery (m16n8k16, fp32 accumulate).

__device__ __forceinline__ void stage_Ah(uint32_t* Ah, const __half* __restrict__ A,
                                         int row0, int M, int tid) {
    #pragma unroll
    for (int it = 0; it < 16; it++) {
        int f = tid + it * 256;
        int m = f >> 5;
        int u = f & 31;
        int gr = row0 + m;
        uint2 raw = make_uint2(0u, 0u);
        if (gr < M) raw = *(const uint2*)(A + (size_t)gr * 128 + u * 4);
        Ah[m * SW + u * 2]     = raw.x;
        Ah[m * SW + u * 2 + 1] = raw.y;
    }
}

__device__ __forceinline__ void stage_WhT(uint32_t* Wh, const float* __restrict__ W,
                                          int tid) {
    int n = tid & 127;
    int p = tid >> 7;
    #pragma unroll
    for (int w = 0; w < 32; w++) {
        int word = p * 32 + w;
        int k = word * 2;
        float lo = __ldg(&W[(size_t)k * 128 + n]);
        float hi = __ldg(&W[(size_t)(k + 1) * 128 + n]);
        __half2 hh = __float22half2_rn(make_float2(lo, hi));
        Wh[n * SW + word] = *(uint32_t*)&hh;
    }
}

__device__ __forceinline__ void mma_fullk(const uint32_t* Ah, const uint32_t* Wh,
                                          float c[2][8][4],
                                          int wm, int wn, int lg, int lt) {
    #pragma unroll
    for (int kw = 0; kw < 64; kw += 8) {
        uint32_t af[2][4];
        #pragma unroll
        for (int mt = 0; mt < 2; mt++) {
            int m = wm * 32 + mt * 16 + lg;
            const uint32_t* r0 = Ah + m * SW + kw;
            const uint32_t* r1 = Ah + (m + 8) * SW + kw;
            af[mt][0] = r0[lt];
            af[mt][1] = r1[lt];
            af[mt][2] = r0[lt + 4];
            af[mt][3] = r1[lt + 4];
        }
        #pragma unroll
        for (int nt = 0; nt < 8; nt++) {
            int n = wn * 64 + nt * 8 + lg;
            uint32_t b0 = Wh[n * SW + kw + lt];
            uint32_t b1 = Wh[n * SW + kw + 4 + lt];
            #pragma unroll
            for (int mt = 0; mt < 2; mt++) {
                asm volatile(
                    "mma.sync.aligned.m16n8k16.row.col.f32.f16.f16.f32 "
                    "{%0,%1,%2,%3}, {%4,%5,%6,%7}, {%8,%9}, {%0,%1,%2,%3};"
                    : "+f"(c[mt][nt][0]), "+f"(c[mt][nt][1]),
                      "+f"(c[mt][nt][2]), "+f"(c[mt][nt][3])
                    : "r"(af[mt][0]), "r"(af[mt][1]),
                      "r"(af[mt][2]), "r"(af[mt][3]),
                      "r"(b0), "r"(b1));
            }
        }
    }
}

// GEMM: C16[r] = norm_src[r] * relu(A16 @ W + bias)[r]
// (pre-scales rows for the following weightless SpMM)
__global__ void __launch_bounds__(256)
k_gemm_tc16(const __half* __restrict__ A, const float* __restrict__ W,
            const float* __restrict__ bias, __half* __restrict__ C, int M) {
    extern __shared__ uint32_t sm[];
    uint32_t* Ah = sm;
    uint32_t* Wh = sm + 128 * SW;
    int tid  = threadIdx.x;
    int warp = tid >> 5, lane = tid & 31;
    int wm = warp & 3, wn = warp >> 2;
    int lg = lane >> 2, lt = lane & 3;
    int row0 = blockIdx.x * 128;

    stage_Ah(Ah, A, row0, M, tid);
    stage_WhT(Wh, W, tid);
    __syncthreads();

    float c[2][8][4] = {};
    mma_fullk(Ah, Wh, c, wm, wn, lg, lt);

    // per-row norm_src for pre-scaling
    float ns[2][2];
    #pragma unroll
    for (int mt = 0; mt < 2; mt++) {
        int r = row0 + wm * 32 + mt * 16 + lg;
        ns[mt][0] = (r < M)     ? __ldg(&g_norm_src[r])     : 0.f;
        ns[mt][1] = (r + 8 < M) ? __ldg(&g_norm_src[r + 8]) : 0.f;
    }

    #pragma unroll
    for (int nt = 0; nt < 8; nt++) {
        int col = wn * 64 + nt * 8 + 2 * lt;
        float2 bv = *(const float2*)(bias + col);
        #pragma unroll
        for (int mt = 0; mt < 2; mt++) {
            int r = row0 + wm * 32 + mt * 16 + lg;
            float2 o0, o1;
            o0.x = ns[mt][0] * fmaxf(c[mt][nt][0] + bv.x, 0.f);
            o0.y = ns[mt][0] * fmaxf(c[mt][nt][1] + bv.y, 0.f);
            o1.x = ns[mt][1] * fmaxf(c[mt][nt][2] + bv.x, 0.f);
            o1.y = ns[mt][1] * fmaxf(c[mt][nt][3] + bv.y, 0.f);
            if (r < M)     *(__half2*)(C + (size_t)r * 128 + col)       = __float22half2_rn(o0);
            if (r + 8 < M) *(__half2*)(C + (size_t)(r + 8) * 128 + col) = __float22half2_rn(o1);
        }
    }
}

// ---------------------------------------------------------------
// Fused layer3 + head: h = relu(A16 @ W3 + b3) kept in smem (fp16),
// then out[r] = relu(h @ Wo1 + bo1) . w2 + b2.  (no norm pre-scale here)
__global__ void __launch_bounds__(256)
k_gemm3_head(const __half* __restrict__ A, const float* __restrict__ W3,
             const float* __restrict__ b3, const float* __restrict__ Wo1,
             const float* __restrict__ bo1, const float* __restrict__ w2,
             const float* __restrict__ b2, float* __restrict__ out, int M) {
    extern __shared__ uint32_t sm[];
    uint32_t* Ah = sm;               // phase-1 A tile; reused as h tile
    uint32_t* Wh = sm + 128 * SW;    // phase-1 W3^T; reused for Wo1^T
    __shared__ float red[128];
    __shared__ float w2s[128];

    int tid  = threadIdx.x;
    int warp = tid >> 5, lane = tid & 31;
    int wm = warp & 3, wn = warp >> 2;
    int lg = lane >> 2, lt = lane & 3;
    int row0 = blockIdx.x * 128;

    if (tid < 128) { red[tid] = 0.f; w2s[tid] = w2[tid]; }

    // phase 1: c = A @ W3
    stage_Ah(Ah, A, row0, M, tid);
    stage_WhT(Wh, W3, tid);
    __syncthreads();
    float c[2][8][4] = {};
    mma_fullk(Ah, Wh, c, wm, wn, lg, lt);
    __syncthreads();

    // phase 1.5: h = relu(c + b3) -> Ah as fp16 [m][k]; stage Wo1^T -> Wh
    #pragma unroll
    for (int nt = 0; nt < 8; nt++) {
        int col = wn * 64 + nt * 8 + 2 * lt;
        float2 bv = *(const float2*)(b3 + col);
        int widx = col >> 1;
        #pragma unroll
        for (int mt = 0; mt < 2; mt++) {
            int r = wm * 32 + mt * 16 + lg;
            __half2 h0 = __float22half2_rn(make_float2(
                fmaxf(c[mt][nt][0] + bv.x, 0.f), fmaxf(c[mt][nt][1] + bv.y, 0.f)));
            __half2 h1 = __float22half2_rn(make_float2(
                fmaxf(c[mt][nt][2] + bv.x, 0.f), fmaxf(c[mt][nt][3] + bv.y, 0.f)));
            Ah[r * SW + widx]       = *(uint32_t*)&h0;
            Ah[(r + 8) * SW + widx] = *(uint32_t*)&h1;
        }
    }
    stage_WhT(Wh, Wo1, tid);
    __syncthreads();

    // phase 2: c2 = h @ Wo1
    float c2[2][8][4] = {};
    mma_fullk(Ah, Wh, c2, wm, wn, lg, lt);

    // head epilogue: relu(c2 + bo1) . w2 -> reduce -> out
    #pragma unroll
    for (int mt = 0; mt < 2; mt++) {
        float dot0 = 0.f, dot1 = 0.f;
        #pragma unroll
        for (int nt = 0; nt < 8; nt++) {
            int col = wn * 64 + nt * 8 + 2 * lt;
            float2 bv = *(const float2*)(bo1 + col);
            float wa = w2s[col], wb = w2s[col + 1];
            dot0 += fmaxf(c2[mt][nt][0] + bv.x, 0.f) * wa
                  + fmaxf(c2[mt][nt][1] + bv.y, 0.f) * wb;
            dot1 += fmaxf(c2[mt][nt][2] + bv.x, 0.f) * wa
                  + fmaxf(c2[mt][nt][3] + bv.y, 0.f) * wb;
        }
        int rl = wm * 32 + mt * 16 + lg;
        atomicAdd(&red[rl], dot0);
        atomicAdd(&red[rl + 8], dot1);
    }
    __syncthreads();
    if (tid < 128 && row0 + tid < M)
        out[row0 + tid] = red[tid] + b2[0];
}

// ---------------------------------------------------------------
extern "C" void kernel_launch(void* const* d_in, const int* in_sizes, int n_in,
                              void* d_out, int out_size) {
    const float* nf   = (const float*)d_in[0];
    const int*   src  = (const int*)d_in[1];
    const int*   dst  = (const int*)d_in[2];
    const float* Wemb = (const float*)d_in[3];
    const float* bemb = (const float*)d_in[4];
    const float* Wg   = (const float*)d_in[5];
    const float* bg   = (const float*)d_in[6];
    const float* Wo1  = (const float*)d_in[7];
    const float* bo1  = (const float*)d_in[8];
    const float* Wo2  = (const float*)d_in[9];
    const float* bo2  = (const float*)d_in[10];
    float* out = (float*)d_out;

    __half *agg, *h16;
    cudaGetSymbolAddress((void**)&agg, g_agg);
    cudaGetSymbolAddress((void**)&h16, g_h16);

    const int SM_GEMM = 2 * 128 * SW * 4;   // 69632 bytes
    cudaFuncSetAttribute(k_gemm_tc16,
                         cudaFuncAttributeMaxDynamicSharedMemorySize, SM_GEMM);
    cudaFuncSetAttribute(k_gemm3_head,
                         cudaFuncAttributeMaxDynamicSharedMemorySize, SM_GEMM);

    const int NB_EDGE2 = (NE / 2 + 255) / 256;   // 2 edges per thread
    const int NB_WARP = (NN * 32 + 255) / 256;   // warp-per-node kernels

    k_count<<<NB_EDGE2, 256>>>(src, dst);                       // 0
    k_scanA<<<SCAN_BLOCKS, 256>>>();                            // 1
    k_scanB<<<SCAN_BLOCKS, 256>>>();                            // 2
    k_fill<<<NB_EDGE2, 256>>>(src, dst);                        // 3

    // layer 1: fused embed+aggregate -> agg, then GEMM (pre-scaled) -> h16
    k_spmm_l1<<<NB_WARP, 256>>>(nf, Wemb, bemb, agg);           // 4
    k_gemm_tc16<<<NB_TILE, 256, SM_GEMM>>>(agg, Wg, bg, h16, NN);        // 5

    // layer 2
    k_spmm16<<<NB_WARP, 256>>>(h16, agg);                       // 6
    k_gemm_tc16<<<NB_TILE, 256, SM_GEMM>>>(agg, Wg + 128 * 128,
                                           bg + 128, h16, NN);  // 7
    // layer 3 aggregate
    k_spmm16<<<NB_WARP, 256>>>(h16, agg);                       // 8

    // fused layer-3 GEMM + head -> out
    k_gemm3_head<<<NB_TILE, 256, SM_GEMM>>>(agg, Wg + 2 * 128 * 128,
                                            bg + 2 * 128, Wo1, bo1,
                                            Wo2, bo2, out, NN);  // 9
}